// round 3
// baseline (speedup 1.0000x reference)
#include <cuda_runtime.h>
#include <cuda_fp16.h>
#include <cstdint>
#include <cstddef>

#define ATOMS   50000
#define EDGES   800000
#define NB      128     // n_atom_basis == n_filters
#define NG      64      // n_gauss
#define TS      4096    // filter table samples over [0, CUTOFF]
#define CUTOFFF 5.0f
#define ASTR    132     // smem stride (words) for A tiles
#define BSTR    136     // smem stride (words) for B tiles

// Scratch (no allocations allowed in kernel_launch)
__device__ __half2 g_tabh[(size_t)TS * NB];     // 2 MB  (value, delta) per column
__device__ float   g_rf [(size_t)ATOMS * NB];   // 25.6MB r @ W_af
__device__ float   g_acc[(size_t)ATOMS * NB];   // 25.6MB segment-sum accumulator

// ---------------------------------------------------------------------------
__global__ void zero_acc_kernel() {
    size_t n4 = (size_t)ATOMS * NB / 4;
    float4 z = make_float4(0.f, 0.f, 0.f, 0.f);
    float4* p = reinterpret_cast<float4*>(g_acc);
    for (size_t i = blockIdx.x * (size_t)blockDim.x + threadIdx.x; i < n4;
         i += (size_t)gridDim.x * blockDim.x)
        p[i] = z;
}

// ---------------------------------------------------------------------------
// Build packed fp16 table: tabh[i][c] = (W(d_i)[c], W(d_{i+1})[c]-W(d_i)[c])
// where W(d) = exp(coeff*(d - off)^2) @ W_df2 + b_df2. One warp per row,
// lane owns 4 columns.
__global__ void build_table_kernel(const float* __restrict__ Wdf2,
                                   const float* __restrict__ bdf2) {
    int row  = blockIdx.x * 4 + (threadIdx.x >> 5);
    int lane = threadIdx.x & 31;
    if (row >= TS) return;
    const float step  = CUTOFFF / (float)(TS - 1);
    const float width = 5.0f / 63.0f;
    const float coeff = -0.5f / (width * width);
    float d0 = (float)row * step;
    float d1 = d0 + step;
    float4 a0 = reinterpret_cast<const float4*>(bdf2)[lane];
    float4 a1 = a0;
    #pragma unroll 8
    for (int k = 0; k < NG; k++) {
        float off = (float)k * (5.0f / 63.0f);
        float e0 = d0 - off, e1 = d1 - off;
        float g0 = __expf(coeff * e0 * e0);
        float g1 = __expf(coeff * e1 * e1);
        float4 w = reinterpret_cast<const float4*>(Wdf2 + k * NB)[lane];
        a0.x += g0 * w.x; a0.y += g0 * w.y; a0.z += g0 * w.z; a0.w += g0 * w.w;
        a1.x += g1 * w.x; a1.y += g1 * w.y; a1.z += g1 * w.z; a1.w += g1 * w.w;
    }
    __half2 h[4];
    h[0] = __floats2half2_rn(a0.x, a1.x - a0.x);
    h[1] = __floats2half2_rn(a0.y, a1.y - a0.y);
    h[2] = __floats2half2_rn(a0.z, a1.z - a0.z);
    h[3] = __floats2half2_rn(a0.w, a1.w - a0.w);
    *reinterpret_cast<uint4*>(g_tabh + (size_t)row * NB + lane * 4) =
        *reinterpret_cast<uint4*>(h);
}

// ---------------------------------------------------------------------------
// Edge kernel: warp per edge. Single 16B load per lane gives (value, delta)
// for its 4 filter columns; lerp in fp32; gather rf[src]; vector-atomic add.
__global__ void edge_kernel(const float* __restrict__ dist,
                            const int*   __restrict__ idx,
                            int E) {
    int lane   = threadIdx.x & 31;
    int warp   = (blockIdx.x * blockDim.x + threadIdx.x) >> 5;
    int nwarps = (gridDim.x * blockDim.x) >> 5;
    const float scale = (float)(TS - 1) / CUTOFFF;
    for (int e = warp; e < E; e += nwarps) {
        float d = __ldg(&dist[e]);
        int2 de = *reinterpret_cast<const int2*>(idx + 2 * (size_t)e);
        int dst = de.x, src = de.y;
        float pos = d * scale;
        int i = (int)pos;
        if (i > TS - 2) i = TS - 2;
        if (i < 0) i = 0;
        float f = pos - (float)i;
        uint4 t = *reinterpret_cast<const uint4*>(
            g_tabh + (size_t)i * NB + lane * 4);
        const __half2* h = reinterpret_cast<const __half2*>(&t);
        float2 p0 = __half22float2(h[0]);
        float2 p1 = __half22float2(h[1]);
        float2 p2 = __half22float2(h[2]);
        float2 p3 = __half22float2(h[3]);
        float4 rv = reinterpret_cast<const float4*>(g_rf + (size_t)src * NB)[lane];
        float4 v;
        v.x = fmaf(f, p0.y, p0.x) * rv.x;
        v.y = fmaf(f, p1.y, p1.x) * rv.y;
        v.z = fmaf(f, p2.y, p2.x) * rv.z;
        v.w = fmaf(f, p3.y, p3.x) * rv.w;
        float* dp = g_acc + (size_t)dst * NB + lane * 4;
        asm volatile("red.global.add.v4.f32 [%0], {%1,%2,%3,%4};"
                     :: "l"(dp), "f"(v.x), "f"(v.y), "f"(v.z), "f"(v.w)
                     : "memory");
    }
}

// ---------------------------------------------------------------------------
__device__ __forceinline__ float sspf(float x) {
    float ax = fabsf(x);
    return fmaxf(x, 0.0f) + log1pf(__expf(-ax)) - 0.69314718f;
}

__device__ __forceinline__ uint32_t f2tf32(float x) {
    uint32_t r;
    asm("cvt.rna.tf32.f32 %0, %1;" : "=r"(r) : "f"(x));
    return r;
}
// Split fp32 into hi+lo tf32 operands (hi bit-pattern is a valid fp32).
__device__ __forceinline__ void split_tf32(float x, uint32_t& hi, uint32_t& lo) {
    hi = f2tf32(x);
    lo = f2tf32(x - __uint_as_float(hi));
}

__device__ __forceinline__ void mma_tf32(float* c, const uint32_t* a,
                                         uint32_t b0, uint32_t b1) {
    asm volatile(
        "mma.sync.aligned.m16n8k8.row.col.f32.tf32.tf32.f32 "
        "{%0,%1,%2,%3}, {%4,%5,%6,%7}, {%8,%9}, {%0,%1,%2,%3};"
        : "+f"(c[0]), "+f"(c[1]), "+f"(c[2]), "+f"(c[3])
        : "r"(a[0]), "r"(a[1]), "r"(a[2]), "r"(a[3]), "r"(b0), "r"(b1));
}

// One 128x128x128 tile pass with 3-term split-tf32 (full fp32 accuracy).
// As: fp32 [128][ASTR], Bs: fp32 [128][BSTR]. Result in acc frags.
__device__ __forceinline__ void mma_tile_3term(const float* As, const float* Bs,
                                               int wm, int wn, int g, int tig,
                                               float acc[2][8][4]) {
    #pragma unroll
    for (int mt = 0; mt < 2; mt++)
        #pragma unroll
        for (int nt = 0; nt < 8; nt++)
            #pragma unroll
            for (int j = 0; j < 4; j++) acc[mt][nt][j] = 0.f;

    #pragma unroll
    for (int k0 = 0; k0 < 128; k0 += 8) {
        uint32_t ah[2][4], al[2][4];
        #pragma unroll
        for (int mt = 0; mt < 2; mt++) {
            int r = wm * 32 + mt * 16;
            split_tf32(As[(r + g)     * ASTR + k0 + tig],     ah[mt][0], al[mt][0]);
            split_tf32(As[(r + g + 8) * ASTR + k0 + tig],     ah[mt][1], al[mt][1]);
            split_tf32(As[(r + g)     * ASTR + k0 + tig + 4], ah[mt][2], al[mt][2]);
            split_tf32(As[(r + g + 8) * ASTR + k0 + tig + 4], ah[mt][3], al[mt][3]);
        }
        #pragma unroll
        for (int nt = 0; nt < 8; nt++) {
            int n = wn * 64 + nt * 8;
            uint32_t bh0, bl0, bh1, bl1;
            split_tf32(Bs[(k0 + tig)     * BSTR + n + g], bh0, bl0);
            split_tf32(Bs[(k0 + tig + 4) * BSTR + n + g], bh1, bl1);
            #pragma unroll
            for (int mt = 0; mt < 2; mt++) {
                mma_tf32(acc[mt][nt], al[mt], bh0, bh1);
                mma_tf32(acc[mt][nt], ah[mt], bl0, bl1);
                mma_tf32(acc[mt][nt], ah[mt], bh0, bh1);
            }
        }
    }
}

// Stage helpers
__device__ __forceinline__ void stage_B(const float* __restrict__ B, float* Bs,
                                        int tid) {
    for (int i = tid; i < 128 * 32; i += 256) {
        int r = i >> 5, c = i & 31;
        reinterpret_cast<float4*>(Bs + r * BSTR)[c] =
            reinterpret_cast<const float4*>(B + r * NB)[c];
    }
}
__device__ __forceinline__ void stage_A(const float* __restrict__ A, float* As,
                                        int tid, int row0, int M) {
    for (int i = tid; i < 128 * 32; i += 256) {
        int r = i >> 5, c = i & 31;
        float4 v = make_float4(0.f, 0.f, 0.f, 0.f);
        if (row0 + r < M)
            v = reinterpret_cast<const float4*>(A + (size_t)(row0 + r) * NB)[c];
        reinterpret_cast<float4*>(As + r * ASTR)[c] = v;
    }
}

// ---------------------------------------------------------------------------
// Single GEMM: C = A @ B (no bias/act) — used for rf = r @ W_af.
__global__ __launch_bounds__(256, 1)
void gemm3t_kernel(const float* __restrict__ A, const float* __restrict__ B,
                   float* __restrict__ C, int M) {
    extern __shared__ float sm[];
    float* As = sm;
    float* Bs = sm + 128 * ASTR;
    int tid = threadIdx.x, row0 = blockIdx.x * 128;
    stage_B(B, Bs, tid);
    stage_A(A, As, tid, row0, M);
    __syncthreads();

    int warp = tid >> 5, lane = tid & 31;
    int wm = warp & 3, wn = warp >> 2;
    int g = lane >> 2, tig = lane & 3;
    float acc[2][8][4];
    mma_tile_3term(As, Bs, wm, wn, g, tig, acc);

    #pragma unroll
    for (int mt = 0; mt < 2; mt++)
        #pragma unroll
        for (int nt = 0; nt < 8; nt++) {
            int col = wn * 64 + nt * 8 + 2 * tig;
            int r1 = row0 + wm * 32 + mt * 16 + g, r2 = r1 + 8;
            if (r1 < M)
                *reinterpret_cast<float2*>(C + (size_t)r1 * NB + col) =
                    make_float2(acc[mt][nt][0], acc[mt][nt][1]);
            if (r2 < M)
                *reinterpret_cast<float2*>(C + (size_t)r2 * NB + col) =
                    make_float2(acc[mt][nt][2], acc[mt][nt][3]);
        }
}

// ---------------------------------------------------------------------------
// Fused GEMM2+GEMM3: out = ssp(A@W1+b1) @ W2 + b2.
// mid tile exchanged through As smem between the two MMA passes.
__global__ __launch_bounds__(256, 1)
void gemm23_kernel(const float* __restrict__ A,
                   const float* __restrict__ W1, const float* __restrict__ b1,
                   const float* __restrict__ W2, const float* __restrict__ b2,
                   float* __restrict__ C, int M) {
    extern __shared__ float sm[];
    float* As  = sm;                         // [128][ASTR]
    float* B1s = sm + 128 * ASTR;            // [128][BSTR]
    float* B2s = B1s + 128 * BSTR;           // [128][BSTR]
    int tid = threadIdx.x, row0 = blockIdx.x * 128;
    stage_B(W1, B1s, tid);
    stage_B(W2, B2s, tid);
    stage_A(A, As, tid, row0, M);
    __syncthreads();

    int warp = tid >> 5, lane = tid & 31;
    int wm = warp & 3, wn = warp >> 2;
    int g = lane >> 2, tig = lane & 3;
    float acc[2][8][4];

    // Pass 1: mid = ssp(A @ W1 + b1)
    mma_tile_3term(As, B1s, wm, wn, g, tig, acc);
    __syncthreads();   // everyone done reading As
    #pragma unroll
    for (int mt = 0; mt < 2; mt++)
        #pragma unroll
        for (int nt = 0; nt < 8; nt++) {
            int col = wn * 64 + nt * 8 + 2 * tig;
            float2 bv = *reinterpret_cast<const float2*>(b1 + col);
            int r1 = wm * 32 + mt * 16 + g, r2 = r1 + 8;
            *reinterpret_cast<float2*>(&As[r1 * ASTR + col]) =
                make_float2(sspf(acc[mt][nt][0] + bv.x),
                            sspf(acc[mt][nt][1] + bv.y));
            *reinterpret_cast<float2*>(&As[r2 * ASTR + col]) =
                make_float2(sspf(acc[mt][nt][2] + bv.x),
                            sspf(acc[mt][nt][3] + bv.y));
        }
    __syncthreads();

    // Pass 2: out = mid @ W2 + b2
    mma_tile_3term(As, B2s, wm, wn, g, tig, acc);
    #pragma unroll
    for (int mt = 0; mt < 2; mt++)
        #pragma unroll
        for (int nt = 0; nt < 8; nt++) {
            int col = wn * 64 + nt * 8 + 2 * tig;
            float2 bv = *reinterpret_cast<const float2*>(b2 + col);
            int r1 = row0 + wm * 32 + mt * 16 + g, r2 = r1 + 8;
            if (r1 < M)
                *reinterpret_cast<float2*>(C + (size_t)r1 * NB + col) =
                    make_float2(acc[mt][nt][0] + bv.x, acc[mt][nt][1] + bv.y);
            if (r2 < M)
                *reinterpret_cast<float2*>(C + (size_t)r2 * NB + col) =
                    make_float2(acc[mt][nt][2] + bv.x, acc[mt][nt][3] + bv.y);
        }
}

// ---------------------------------------------------------------------------
extern "C" void kernel_launch(void* const* d_in, const int* in_sizes, int n_in,
                              void* d_out, int out_size) {
    const float* r     = (const float*)d_in[0];
    const float* e     = (const float*)d_in[1];
    const int*   a     = (const int*)  d_in[2];
    // d_in[3], d_in[4] = W_df1, b_df1: dead in the reference (overwritten)
    const float* W_df2 = (const float*)d_in[5];
    const float* b_df2 = (const float*)d_in[6];
    const float* W_af  = (const float*)d_in[7];
    const float* W_d1  = (const float*)d_in[8];
    const float* b_d1  = (const float*)d_in[9];
    const float* W_d2  = (const float*)d_in[10];
    const float* b_d2  = (const float*)d_in[11];
    float* out = (float*)d_out;

    float *rf, *acc;
    cudaGetSymbolAddress((void**)&rf,  g_rf);
    cudaGetSymbolAddress((void**)&acc, g_acc);

    const int smem1 = (128 * ASTR + 128 * BSTR) * 4;       // 137216 B
    const int smem2 = (128 * ASTR + 2 * 128 * BSTR) * 4;   // 206848 B
    cudaFuncSetAttribute(gemm3t_kernel,
                         cudaFuncAttributeMaxDynamicSharedMemorySize, smem1);
    cudaFuncSetAttribute(gemm23_kernel,
                         cudaFuncAttributeMaxDynamicSharedMemorySize, smem2);

    int E = in_sizes[1];          // 800000
    int M = in_sizes[0] / NB;     // 50000
    int nblk = (M + 127) / 128;   // 391

    zero_acc_kernel<<<512, 256>>>();
    build_table_kernel<<<TS / 4, 128>>>(W_df2, b_df2);
    gemm3t_kernel<<<nblk, 256, smem1>>>(r, W_af, rf, M);
    edge_kernel<<<2048, 256>>>(e, a, E);
    gemm23_kernel<<<nblk, 256, smem2>>>(acc, W_d1, b_d1, W_d2, b_d2, out, M);
}

// round 4
// speedup vs baseline: 1.5781x; 1.5781x over previous
#include <cuda_runtime.h>
#include <cuda_fp16.h>
#include <cstdint>
#include <cstddef>

#define ATOMS   50000
#define EDGES   800000
#define NB      128     // n_atom_basis == n_filters
#define NG      64      // n_gauss
#define TS      4096    // filter table samples over [0, CUTOFF]
#define CUTOFFF 5.0f
#define ASTR    132     // smem stride (words) for A tiles (64 rows)
#define BSTR    136     // smem stride (words) for B tiles (128 rows)
#define TILEM   64      // block tile rows

// Scratch (no allocations allowed in kernel_launch)
__device__ __half2 g_tabh[(size_t)TS * NB];     // 2 MB  (value, delta) per column
__device__ float   g_rf [(size_t)ATOMS * NB];   // 25.6MB r @ W_af
__device__ float   g_acc[(size_t)ATOMS * NB];   // 25.6MB segment-sum accumulator

// ---------------------------------------------------------------------------
__global__ void zero_acc_kernel() {
    size_t n4 = (size_t)ATOMS * NB / 4;
    float4 z = make_float4(0.f, 0.f, 0.f, 0.f);
    float4* p = reinterpret_cast<float4*>(g_acc);
    for (size_t i = blockIdx.x * (size_t)blockDim.x + threadIdx.x; i < n4;
         i += (size_t)gridDim.x * blockDim.x)
        p[i] = z;
}

// ---------------------------------------------------------------------------
// Build packed fp16 table: tabh[i][c] = (W(d_i)[c], W(d_{i+1})[c]-W(d_i)[c])
__global__ void build_table_kernel(const float* __restrict__ Wdf2,
                                   const float* __restrict__ bdf2) {
    int row  = blockIdx.x * 4 + (threadIdx.x >> 5);
    int lane = threadIdx.x & 31;
    if (row >= TS) return;
    const float step  = CUTOFFF / (float)(TS - 1);
    const float width = 5.0f / 63.0f;
    const float coeff = -0.5f / (width * width);
    float d0 = (float)row * step;
    float d1 = d0 + step;
    float4 a0 = reinterpret_cast<const float4*>(bdf2)[lane];
    float4 a1 = a0;
    #pragma unroll 8
    for (int k = 0; k < NG; k++) {
        float off = (float)k * (5.0f / 63.0f);
        float e0 = d0 - off, e1 = d1 - off;
        float g0 = __expf(coeff * e0 * e0);
        float g1 = __expf(coeff * e1 * e1);
        float4 w = reinterpret_cast<const float4*>(Wdf2 + k * NB)[lane];
        a0.x += g0 * w.x; a0.y += g0 * w.y; a0.z += g0 * w.z; a0.w += g0 * w.w;
        a1.x += g1 * w.x; a1.y += g1 * w.y; a1.z += g1 * w.z; a1.w += g1 * w.w;
    }
    __half2 h[4];
    h[0] = __floats2half2_rn(a0.x, a1.x - a0.x);
    h[1] = __floats2half2_rn(a0.y, a1.y - a0.y);
    h[2] = __floats2half2_rn(a0.z, a1.z - a0.z);
    h[3] = __floats2half2_rn(a0.w, a1.w - a0.w);
    *reinterpret_cast<uint4*>(g_tabh + (size_t)row * NB + lane * 4) =
        *reinterpret_cast<uint4*>(h);
}

// ---------------------------------------------------------------------------
// Edge kernel (R3, unchanged): warp per edge; single 16B table load per lane,
// lerp in fp32, gather rf[src], vector-atomic add into acc[dst].
__global__ void edge_kernel(const float* __restrict__ dist,
                            const int*   __restrict__ idx,
                            int E) {
    int lane   = threadIdx.x & 31;
    int warp   = (blockIdx.x * blockDim.x + threadIdx.x) >> 5;
    int nwarps = (gridDim.x * blockDim.x) >> 5;
    const float scale = (float)(TS - 1) / CUTOFFF;
    for (int e = warp; e < E; e += nwarps) {
        float d = __ldg(&dist[e]);
        int2 de = *reinterpret_cast<const int2*>(idx + 2 * (size_t)e);
        int dst = de.x, src = de.y;
        float pos = d * scale;
        int i = (int)pos;
        if (i > TS - 2) i = TS - 2;
        if (i < 0) i = 0;
        float f = pos - (float)i;
        uint4 t = *reinterpret_cast<const uint4*>(
            g_tabh + (size_t)i * NB + lane * 4);
        const __half2* h = reinterpret_cast<const __half2*>(&t);
        float2 p0 = __half22float2(h[0]);
        float2 p1 = __half22float2(h[1]);
        float2 p2 = __half22float2(h[2]);
        float2 p3 = __half22float2(h[3]);
        float4 rv = reinterpret_cast<const float4*>(g_rf + (size_t)src * NB)[lane];
        float4 v;
        v.x = fmaf(f, p0.y, p0.x) * rv.x;
        v.y = fmaf(f, p1.y, p1.x) * rv.y;
        v.z = fmaf(f, p2.y, p2.x) * rv.z;
        v.w = fmaf(f, p3.y, p3.x) * rv.w;
        float* dp = g_acc + (size_t)dst * NB + lane * 4;
        asm volatile("red.global.add.v4.f32 [%0], {%1,%2,%3,%4};"
                     :: "l"(dp), "f"(v.x), "f"(v.y), "f"(v.z), "f"(v.w)
                     : "memory");
    }
}

// ---------------------------------------------------------------------------
__device__ __forceinline__ float sspf(float x) {
    float ax = fabsf(x);
    return fmaxf(x, 0.0f) + log1pf(__expf(-ax)) - 0.69314718f;
}

__device__ __forceinline__ uint32_t f2tf32(float x) {
    uint32_t r;
    asm("cvt.rna.tf32.f32 %0, %1;" : "=r"(r) : "f"(x));
    return r;
}

__device__ __forceinline__ void mma_tf32(float* c, const uint32_t* a,
                                         uint32_t b0, uint32_t b1) {
    asm volatile(
        "mma.sync.aligned.m16n8k8.row.col.f32.tf32.tf32.f32 "
        "{%0,%1,%2,%3}, {%4,%5,%6,%7}, {%8,%9}, {%0,%1,%2,%3};"
        : "+f"(c[0]), "+f"(c[1]), "+f"(c[2]), "+f"(c[3])
        : "r"(a[0]), "r"(a[1]), "r"(a[2]), "r"(a[3]), "r"(b0), "r"(b1));
}

// Stage B[128,128] (tf32-converted) into Bs[128][BSTR]
__device__ __forceinline__ void stage_B(const float* __restrict__ B,
                                        uint32_t* Bs, int tid) {
    for (int i = tid; i < 128 * 32; i += 256) {
        int r = i >> 5, c = i & 31;
        float4 v = reinterpret_cast<const float4*>(B + r * NB)[c];
        uint4 t = make_uint4(f2tf32(v.x), f2tf32(v.y), f2tf32(v.z), f2tf32(v.w));
        *reinterpret_cast<uint4*>(&Bs[r * BSTR + c * 4]) = t;
    }
}
// Stage A tile [TILEM,128] (tf32-converted, zero-padded past M)
__device__ __forceinline__ void stage_A(const float* __restrict__ A,
                                        uint32_t* As, int tid, int row0, int M) {
    for (int i = tid; i < TILEM * 32; i += 256) {
        int r = i >> 5, c = i & 31;
        float4 v = make_float4(0.f, 0.f, 0.f, 0.f);
        if (row0 + r < M)
            v = reinterpret_cast<const float4*>(A + (size_t)(row0 + r) * NB)[c];
        uint4 t = make_uint4(f2tf32(v.x), f2tf32(v.y), f2tf32(v.z), f2tf32(v.w));
        *reinterpret_cast<uint4*>(&As[r * ASTR + c * 4]) = t;
    }
}

// One 64x128x128 tile pass, plain tf32. Warp tile 16x64 (wm = warp&3,
// wn = warp>>2). acc[nt][4] for 8 n-tiles.
__device__ __forceinline__ void mma_tile(const uint32_t* As, const uint32_t* Bs,
                                         int wm, int wn, int g, int tig,
                                         float acc[8][4]) {
    #pragma unroll
    for (int nt = 0; nt < 8; nt++)
        #pragma unroll
        for (int j = 0; j < 4; j++) acc[nt][j] = 0.f;

    #pragma unroll
    for (int k0 = 0; k0 < 128; k0 += 8) {
        uint32_t af[4];
        int r = wm * 16;
        af[0] = As[(r + g)     * ASTR + k0 + tig];
        af[1] = As[(r + g + 8) * ASTR + k0 + tig];
        af[2] = As[(r + g)     * ASTR + k0 + tig + 4];
        af[3] = As[(r + g + 8) * ASTR + k0 + tig + 4];
        #pragma unroll
        for (int nt = 0; nt < 8; nt++) {
            int n = wn * 64 + nt * 8;
            uint32_t b0 = Bs[(k0 + tig)     * BSTR + n + g];
            uint32_t b1 = Bs[(k0 + tig + 4) * BSTR + n + g];
            mma_tf32(acc[nt], af, b0, b1);
        }
    }
}

// ---------------------------------------------------------------------------
// GEMM1: C = A @ B (no bias/act) — rf = r @ W_af.
__global__ __launch_bounds__(256, 2)
void gemm_tf32_kernel(const float* __restrict__ A, const float* __restrict__ B,
                      float* __restrict__ C, int M) {
    extern __shared__ uint32_t smu[];
    uint32_t* As = smu;                  // [TILEM][ASTR]
    uint32_t* Bs = smu + TILEM * ASTR;   // [128][BSTR]
    int tid = threadIdx.x, row0 = blockIdx.x * TILEM;
    stage_B(B, Bs, tid);
    stage_A(A, As, tid, row0, M);
    __syncthreads();

    int warp = tid >> 5, lane = tid & 31;
    int wm = warp & 3, wn = warp >> 2;
    int g = lane >> 2, tig = lane & 3;
    float acc[8][4];
    mma_tile(As, Bs, wm, wn, g, tig, acc);

    #pragma unroll
    for (int nt = 0; nt < 8; nt++) {
        int col = wn * 64 + nt * 8 + 2 * tig;
        int r1 = row0 + wm * 16 + g, r2 = r1 + 8;
        if (r1 < M)
            *reinterpret_cast<float2*>(C + (size_t)r1 * NB + col) =
                make_float2(acc[nt][0], acc[nt][1]);
        if (r2 < M)
            *reinterpret_cast<float2*>(C + (size_t)r2 * NB + col) =
                make_float2(acc[nt][2], acc[nt][3]);
    }
}

// ---------------------------------------------------------------------------
// Fused GEMM2+3: out = ssp(A@W1+b1) @ W2 + b2. Mid tile exchanged via As
// (stored tf32-rounded); W2 restaged over W1's smem after pass 1.
__global__ __launch_bounds__(256, 2)
void gemm23_kernel(const float* __restrict__ A,
                   const float* __restrict__ W1, const float* __restrict__ b1,
                   const float* __restrict__ W2, const float* __restrict__ b2,
                   float* __restrict__ C, int M) {
    extern __shared__ uint32_t smu[];
    uint32_t* As = smu;                  // [TILEM][ASTR]
    uint32_t* Bs = smu + TILEM * ASTR;   // [128][BSTR]
    int tid = threadIdx.x, row0 = blockIdx.x * TILEM;
    stage_B(W1, Bs, tid);
    stage_A(A, As, tid, row0, M);
    __syncthreads();

    int warp = tid >> 5, lane = tid & 31;
    int wm = warp & 3, wn = warp >> 2;
    int g = lane >> 2, tig = lane & 3;
    float acc[8][4];

    // Pass 1: mid = ssp(A @ W1 + b1)
    mma_tile(As, Bs, wm, wn, g, tig, acc);
    __syncthreads();   // everyone done reading As/Bs

    // Write mid (tf32-rounded) into As; restage W2 into Bs
    #pragma unroll
    for (int nt = 0; nt < 8; nt++) {
        int col = wn * 64 + nt * 8 + 2 * tig;
        float2 bv = *reinterpret_cast<const float2*>(b1 + col);
        int r1 = wm * 16 + g, r2 = r1 + 8;
        As[r1 * ASTR + col]     = f2tf32(sspf(acc[nt][0] + bv.x));
        As[r1 * ASTR + col + 1] = f2tf32(sspf(acc[nt][1] + bv.y));
        As[r2 * ASTR + col]     = f2tf32(sspf(acc[nt][2] + bv.x));
        As[r2 * ASTR + col + 1] = f2tf32(sspf(acc[nt][3] + bv.y));
    }
    stage_B(W2, Bs, tid);
    __syncthreads();

    // Pass 2: out = mid @ W2 + b2
    mma_tile(As, Bs, wm, wn, g, tig, acc);
    #pragma unroll
    for (int nt = 0; nt < 8; nt++) {
        int col = wn * 64 + nt * 8 + 2 * tig;
        float2 bv = *reinterpret_cast<const float2*>(b2 + col);
        int r1 = row0 + wm * 16 + g, r2 = r1 + 8;
        if (r1 < M)
            *reinterpret_cast<float2*>(C + (size_t)r1 * NB + col) =
                make_float2(acc[nt][0] + bv.x, acc[nt][1] + bv.y);
        if (r2 < M)
            *reinterpret_cast<float2*>(C + (size_t)r2 * NB + col) =
                make_float2(acc[nt][2] + bv.x, acc[nt][3] + bv.y);
    }
}

// ---------------------------------------------------------------------------
extern "C" void kernel_launch(void* const* d_in, const int* in_sizes, int n_in,
                              void* d_out, int out_size) {
    const float* r     = (const float*)d_in[0];
    const float* e     = (const float*)d_in[1];
    const int*   a     = (const int*)  d_in[2];
    // d_in[3], d_in[4] = W_df1, b_df1: dead in the reference (overwritten)
    const float* W_df2 = (const float*)d_in[5];
    const float* b_df2 = (const float*)d_in[6];
    const float* W_af  = (const float*)d_in[7];
    const float* W_d1  = (const float*)d_in[8];
    const float* b_d1  = (const float*)d_in[9];
    const float* W_d2  = (const float*)d_in[10];
    const float* b_d2  = (const float*)d_in[11];
    float* out = (float*)d_out;

    float *rf, *acc;
    cudaGetSymbolAddress((void**)&rf,  g_rf);
    cudaGetSymbolAddress((void**)&acc, g_acc);

    const int smem = (TILEM * ASTR + 128 * BSTR) * 4;  // 103424 B
    cudaFuncSetAttribute(gemm_tf32_kernel,
                         cudaFuncAttributeMaxDynamicSharedMemorySize, smem);
    cudaFuncSetAttribute(gemm23_kernel,
                         cudaFuncAttributeMaxDynamicSharedMemorySize, smem);

    int E = in_sizes[1];            // 800000
    int M = in_sizes[0] / NB;       // 50000
    int nblk = (M + TILEM - 1) / TILEM;   // 782

    zero_acc_kernel<<<512, 256>>>();
    build_table_kernel<<<TS / 4, 128>>>(W_df2, b_df2);
    gemm_tf32_kernel<<<nblk, 256, smem>>>(r, W_af, rf, M);
    edge_kernel<<<2048, 256>>>(e, a, E);
    gemm23_kernel<<<nblk, 256, smem>>>(acc, W_d1, b_d1, W_d2, b_d2, out, M);
}

// round 7
// speedup vs baseline: 1.7833x; 1.1300x over previous
#include <cuda_runtime.h>
#include <cuda_fp16.h>
#include <cstdint>
#include <cstddef>

#define ATOMS   50000
#define EDGES   800000
#define NB      128     // n_atom_basis == n_filters
#define NG      64      // n_gauss
#define TS      4096    // filter table samples over [0, CUTOFF]
#define CUTOFFF 5.0f
#define ASTR    132     // smem stride (words) for A tiles (64 rows)
#define BSTR    136     // smem stride (words) for B tiles (128 rows)
#define TILEM   64      // row-tile size
#define PGRID   148     // persistent grid (1 CTA/SM on B200)

// Scratch (no allocations allowed in kernel_launch)
__device__ __half2 g_tabh[(size_t)TS * NB];     // 2 MB  (value, delta) per column
__device__ float   g_rf [(size_t)ATOMS * NB];   // 25.6MB r @ W_af
__device__ float   g_acc[(size_t)ATOMS * NB];   // 25.6MB segment-sum accumulator

// ---------------------------------------------------------------------------
__device__ __forceinline__ uint32_t smem_u32(const void* p) {
    uint32_t a;
    asm("{ .reg .u64 t; cvta.to.shared.u64 t, %1; cvt.u32.u64 %0, t; }"
        : "=r"(a) : "l"(p));
    return a;
}

// ---------------------------------------------------------------------------
__global__ void zero_acc_kernel() {
    size_t n4 = (size_t)ATOMS * NB / 4;
    float4 z = make_float4(0.f, 0.f, 0.f, 0.f);
    float4* p = reinterpret_cast<float4*>(g_acc);
    for (size_t i = blockIdx.x * (size_t)blockDim.x + threadIdx.x; i < n4;
         i += (size_t)gridDim.x * blockDim.x)
        p[i] = z;
}

// ---------------------------------------------------------------------------
// Build packed fp16 table: tabh[i][c] = (W(d_i)[c], W(d_{i+1})[c]-W(d_i)[c])
__global__ void build_table_kernel(const float* __restrict__ Wdf2,
                                   const float* __restrict__ bdf2) {
    int row  = blockIdx.x * 4 + (threadIdx.x >> 5);
    int lane = threadIdx.x & 31;
    if (row >= TS) return;
    const float step  = CUTOFFF / (float)(TS - 1);
    const float width = 5.0f / 63.0f;
    const float coeff = -0.5f / (width * width);
    float d0 = (float)row * step;
    float d1 = d0 + step;
    float4 a0 = reinterpret_cast<const float4*>(bdf2)[lane];
    float4 a1 = a0;
    #pragma unroll 8
    for (int k = 0; k < NG; k++) {
        float off = (float)k * (5.0f / 63.0f);
        float e0 = d0 - off, e1 = d1 - off;
        float g0 = __expf(coeff * e0 * e0);
        float g1 = __expf(coeff * e1 * e1);
        float4 w = reinterpret_cast<const float4*>(Wdf2 + k * NB)[lane];
        a0.x += g0 * w.x; a0.y += g0 * w.y; a0.z += g0 * w.z; a0.w += g0 * w.w;
        a1.x += g1 * w.x; a1.y += g1 * w.y; a1.z += g1 * w.z; a1.w += g1 * w.w;
    }
    __half2 h[4];
    h[0] = __floats2half2_rn(a0.x, a1.x - a0.x);
    h[1] = __floats2half2_rn(a0.y, a1.y - a0.y);
    h[2] = __floats2half2_rn(a0.z, a1.z - a0.z);
    h[3] = __floats2half2_rn(a0.w, a1.w - a0.w);
    *reinterpret_cast<uint4*>(g_tabh + (size_t)row * NB + lane * 4) =
        *reinterpret_cast<uint4*>(h);
}

// ---------------------------------------------------------------------------
// Edge kernel (unchanged since R3): warp per edge.
__global__ void edge_kernel(const float* __restrict__ dist,
                            const int*   __restrict__ idx,
                            int E) {
    int lane   = threadIdx.x & 31;
    int warp   = (blockIdx.x * blockDim.x + threadIdx.x) >> 5;
    int nwarps = (gridDim.x * blockDim.x) >> 5;
    const float scale = (float)(TS - 1) / CUTOFFF;
    for (int e = warp; e < E; e += nwarps) {
        float d = __ldg(&dist[e]);
        int2 de = *reinterpret_cast<const int2*>(idx + 2 * (size_t)e);
        int dst = de.x, src = de.y;
        float pos = d * scale;
        int i = (int)pos;
        if (i > TS - 2) i = TS - 2;
        if (i < 0) i = 0;
        float f = pos - (float)i;
        uint4 t = *reinterpret_cast<const uint4*>(
            g_tabh + (size_t)i * NB + lane * 4);
        const __half2* h = reinterpret_cast<const __half2*>(&t);
        float2 p0 = __half22float2(h[0]);
        float2 p1 = __half22float2(h[1]);
        float2 p2 = __half22float2(h[2]);
        float2 p3 = __half22float2(h[3]);
        float4 rv = reinterpret_cast<const float4*>(g_rf + (size_t)src * NB)[lane];
        float4 v;
        v.x = fmaf(f, p0.y, p0.x) * rv.x;
        v.y = fmaf(f, p1.y, p1.x) * rv.y;
        v.z = fmaf(f, p2.y, p2.x) * rv.z;
        v.w = fmaf(f, p3.y, p3.x) * rv.w;
        float* dp = g_acc + (size_t)dst * NB + lane * 4;
        asm volatile("red.global.add.v4.f32 [%0], {%1,%2,%3,%4};"
                     :: "l"(dp), "f"(v.x), "f"(v.y), "f"(v.z), "f"(v.w)
                     : "memory");
    }
}

// ---------------------------------------------------------------------------
__device__ __forceinline__ float sspf(float x) {
    float ax = fabsf(x);
    return fmaxf(x, 0.0f) + log1pf(__expf(-ax)) - 0.69314718f;
}

__device__ __forceinline__ uint32_t f2tf32(float x) {
    uint32_t r;
    asm("cvt.rna.tf32.f32 %0, %1;" : "=r"(r) : "f"(x));
    return r;
}

__device__ __forceinline__ void mma_tf32(float* c, const uint32_t* a,
                                         uint32_t b0, uint32_t b1) {
    asm volatile(
        "mma.sync.aligned.m16n8k8.row.col.f32.tf32.tf32.f32 "
        "{%0,%1,%2,%3}, {%4,%5,%6,%7}, {%8,%9}, {%0,%1,%2,%3};"
        : "+f"(c[0]), "+f"(c[1]), "+f"(c[2]), "+f"(c[3])
        : "r"(a[0]), "r"(a[1]), "r"(a[2]), "r"(a[3]), "r"(b0), "r"(b1));
}

// Stage B[128,128] fp32 -> tf32 smem tile (once per persistent CTA)
__device__ __forceinline__ void stage_B(const float* __restrict__ B,
                                        uint32_t* Bs, int tid) {
    for (int i = tid; i < 128 * 32; i += 256) {
        int r = i >> 5, c = i & 31;
        float4 v = reinterpret_cast<const float4*>(B + r * NB)[c];
        uint4 t = make_uint4(f2tf32(v.x), f2tf32(v.y), f2tf32(v.z), f2tf32(v.w));
        *reinterpret_cast<uint4*>(&Bs[r * BSTR + c * 4]) = t;
    }
}

// Async prefetch of one A tile (raw fp32), zero-fill past M.
__device__ __forceinline__ void prefetch_A(const float* __restrict__ A,
                                           uint32_t as_addr, int row0, int M,
                                           int tid) {
    for (int i = tid; i < TILEM * 32; i += 256) {
        int r = i >> 5, c4 = (i & 31) << 2;
        int row = row0 + r;
        int srow = (row < M) ? row : (M - 1);
        const float* src = A + (size_t)srow * NB + c4;
        uint32_t dst = as_addr + (uint32_t)(r * ASTR + c4) * 4u;
        uint32_t ssz = (row < M) ? 16u : 0u;
        asm volatile("cp.async.ca.shared.global [%0], [%1], 16, %2;"
                     :: "r"(dst), "l"(src), "r"(ssz) : "memory");
    }
}
#define CP_COMMIT() asm volatile("cp.async.commit_group;" ::: "memory")
#define CP_WAIT1()  asm volatile("cp.async.wait_group 1;" ::: "memory")

// One 64x128x128 tile pass. CVT: A words are raw fp32, convert at load.
// Warp tile 16x64 (wm = warp&3, wn = warp>>2); acc[nt][4] for 8 n-tiles.
template <bool CVT>
__device__ __forceinline__ void mma_tile(const uint32_t* As, const uint32_t* Bs,
                                         int wm, int wn, int g, int tig,
                                         float acc[8][4]) {
    #pragma unroll
    for (int nt = 0; nt < 8; nt++)
        #pragma unroll
        for (int j = 0; j < 4; j++) acc[nt][j] = 0.f;

    #pragma unroll
    for (int k0 = 0; k0 < 128; k0 += 8) {
        uint32_t af[4];
        int r = wm * 16;
        af[0] = As[(r + g)     * ASTR + k0 + tig];
        af[1] = As[(r + g + 8) * ASTR + k0 + tig];
        af[2] = As[(r + g)     * ASTR + k0 + tig + 4];
        af[3] = As[(r + g + 8) * ASTR + k0 + tig + 4];
        if (CVT) {
            #pragma unroll
            for (int j = 0; j < 4; j++)
                af[j] = f2tf32(__uint_as_float(af[j]));
        }
        #pragma unroll
        for (int nt = 0; nt < 8; nt++) {
            int n = wn * 64 + nt * 8;
            uint32_t b0 = Bs[(k0 + tig)     * BSTR + n + g];
            uint32_t b1 = Bs[(k0 + tig + 4) * BSTR + n + g];
            mma_tf32(acc[nt], af, b0, b1);
        }
    }
}

// ---------------------------------------------------------------------------
// Persistent GEMM1: rf = r @ W_af. 1 CTA/SM, B staged once, A double-buffered.
__global__ __launch_bounds__(256, 1)
void gemm_p_kernel(const float* __restrict__ A, const float* __restrict__ B,
                   float* __restrict__ C, int M, int ntiles) {
    extern __shared__ uint32_t smu[];
    uint32_t* As0 = smu;                       // [TILEM][ASTR] raw fp32
    uint32_t* As1 = smu + TILEM * ASTR;
    uint32_t* Bs  = smu + 2 * TILEM * ASTR;    // [128][BSTR] tf32
    uint32_t as_addr0 = smem_u32(As0);
    uint32_t as_addr1 = smem_u32(As1);
    int tid = threadIdx.x;

    stage_B(B, Bs, tid);

    int warp = tid >> 5, lane = tid & 31;
    int wm = warp & 3, wn = warp >> 2;
    int g = lane >> 2, tig = lane & 3;

    int t = blockIdx.x;
    int buf = 0;
    if (t < ntiles) prefetch_A(A, as_addr0, t * TILEM, M, tid);
    CP_COMMIT();

    while (t < ntiles) {
        int tn = t + gridDim.x;
        if (tn < ntiles)
            prefetch_A(A, buf ? as_addr0 : as_addr1, tn * TILEM, M, tid);
        CP_COMMIT();
        CP_WAIT1();
        __syncthreads();

        const uint32_t* Asc = buf ? As1 : As0;
        float acc[8][4];
        mma_tile<true>(Asc, Bs, wm, wn, g, tig, acc);

        int row0 = t * TILEM;
        #pragma unroll
        for (int nt = 0; nt < 8; nt++) {
            int col = wn * 64 + nt * 8 + 2 * tig;
            int r1 = row0 + wm * 16 + g, r2 = r1 + 8;
            if (r1 < M)
                *reinterpret_cast<float2*>(C + (size_t)r1 * NB + col) =
                    make_float2(acc[nt][0], acc[nt][1]);
            if (r2 < M)
                *reinterpret_cast<float2*>(C + (size_t)r2 * NB + col) =
                    make_float2(acc[nt][2], acc[nt][3]);
        }
        __syncthreads();   // all reads of Asc done before it is re-prefetched
        buf ^= 1;
        t = tn;
    }
}

// ---------------------------------------------------------------------------
// Persistent fused GEMM2+3: out = ssp(A@W1+b1) @ W2 + b2.
// B1,B2 staged once; A double-buffered; mid (tf32) overwrites the consumed
// A buffer between the two passes.
__global__ __launch_bounds__(256, 1)
void gemm23_p_kernel(const float* __restrict__ A,
                     const float* __restrict__ W1, const float* __restrict__ b1,
                     const float* __restrict__ W2, const float* __restrict__ b2,
                     float* __restrict__ C, int M, int ntiles) {
    extern __shared__ uint32_t smu[];
    uint32_t* As0 = smu;
    uint32_t* As1 = smu + TILEM * ASTR;
    uint32_t* B1s = smu + 2 * TILEM * ASTR;
    uint32_t* B2s = B1s + 128 * BSTR;
    uint32_t as_addr0 = smem_u32(As0);
    uint32_t as_addr1 = smem_u32(As1);
    int tid = threadIdx.x;

    stage_B(W1, B1s, tid);
    stage_B(W2, B2s, tid);

    int warp = tid >> 5, lane = tid & 31;
    int wm = warp & 3, wn = warp >> 2;
    int g = lane >> 2, tig = lane & 3;

    int t = blockIdx.x;
    int buf = 0;
    if (t < ntiles) prefetch_A(A, as_addr0, t * TILEM, M, tid);
    CP_COMMIT();

    while (t < ntiles) {
        int tn = t + gridDim.x;
        if (tn < ntiles)
            prefetch_A(A, buf ? as_addr0 : as_addr1, tn * TILEM, M, tid);
        CP_COMMIT();
        CP_WAIT1();
        __syncthreads();

        uint32_t* Asc = buf ? As1 : As0;
        float acc[8][4];

        // Pass 1: mid = ssp(A @ W1 + b1)
        mma_tile<true>(Asc, B1s, wm, wn, g, tig, acc);
        __syncthreads();   // all warps done reading raw A before overwrite

        #pragma unroll
        for (int nt = 0; nt < 8; nt++) {
            int col = wn * 64 + nt * 8 + 2 * tig;
            float2 bv = *reinterpret_cast<const float2*>(b1 + col);
            int r1 = wm * 16 + g, r2 = r1 + 8;
            Asc[r1 * ASTR + col]     = f2tf32(sspf(acc[nt][0] + bv.x));
            Asc[r1 * ASTR + col + 1] = f2tf32(sspf(acc[nt][1] + bv.y));
            Asc[r2 * ASTR + col]     = f2tf32(sspf(acc[nt][2] + bv.x));
            Asc[r2 * ASTR + col + 1] = f2tf32(sspf(acc[nt][3] + bv.y));
        }
        __syncthreads();

        // Pass 2: out = mid @ W2 + b2
        mma_tile<false>(Asc, B2s, wm, wn, g, tig, acc);
        int row0 = t * TILEM;
        #pragma unroll
        for (int nt = 0; nt < 8; nt++) {
            int col = wn * 64 + nt * 8 + 2 * tig;
            float2 bv = *reinterpret_cast<const float2*>(b2 + col);
            int r1 = row0 + wm * 16 + g, r2 = r1 + 8;
            if (r1 < M)
                *reinterpret_cast<float2*>(C + (size_t)r1 * NB + col) =
                    make_float2(acc[nt][0] + bv.x, acc[nt][1] + bv.y);
            if (r2 < M)
                *reinterpret_cast<float2*>(C + (size_t)r2 * NB + col) =
                    make_float2(acc[nt][2] + bv.x, acc[nt][3] + bv.y);
        }
        __syncthreads();
        buf ^= 1;
        t = tn;
    }
}

// ---------------------------------------------------------------------------
extern "C" void kernel_launch(void* const* d_in, const int* in_sizes, int n_in,
                              void* d_out, int out_size) {
    const float* r     = (const float*)d_in[0];
    const float* e     = (const float*)d_in[1];
    const int*   a     = (const int*)  d_in[2];
    // d_in[3], d_in[4] = W_df1, b_df1: dead in the reference (overwritten)
    const float* W_df2 = (const float*)d_in[5];
    const float* b_df2 = (const float*)d_in[6];
    const float* W_af  = (const float*)d_in[7];
    const float* W_d1  = (const float*)d_in[8];
    const float* b_d1  = (const float*)d_in[9];
    const float* W_d2  = (const float*)d_in[10];
    const float* b_d2  = (const float*)d_in[11];
    float* out = (float*)d_out;

    float *rf, *acc;
    cudaGetSymbolAddress((void**)&rf,  g_rf);
    cudaGetSymbolAddress((void**)&acc, g_acc);

    const int smem1 = (2 * TILEM * ASTR + 128 * BSTR) * 4;   // 137216 B
    const int smem2 = (2 * TILEM * ASTR + 2 * 128 * BSTR) * 4; // 206848 B
    cudaFuncSetAttribute(gemm_p_kernel,
                         cudaFuncAttributeMaxDynamicSharedMemorySize, smem1);
    cudaFuncSetAttribute(gemm23_p_kernel,
                         cudaFuncAttributeMaxDynamicSharedMemorySize, smem2);

    int E = in_sizes[1];            // 800000
    int M = in_sizes[0] / NB;       // 50000
    int ntiles = (M + TILEM - 1) / TILEM;   // 782

    zero_acc_kernel<<<512, 256>>>();
    build_table_kernel<<<TS / 4, 128>>>(W_df2, b_df2);
    gemm_p_kernel<<<PGRID, 256, smem1>>>(r, W_af, rf, M, ntiles);
    edge_kernel<<<2048, 256>>>(e, a, E);
    gemm23_p_kernel<<<PGRID, 256, smem2>>>(acc, W_d1, b_d1, W_d2, b_d2,
                                           out, M, ntiles);
}

// round 8
// speedup vs baseline: 1.8495x; 1.0371x over previous
#include <cuda_runtime.h>
#include <cuda_fp16.h>
#include <cstdint>
#include <cstddef>

#define ATOMS   50000
#define EDGES   800000
#define NB      128     // n_atom_basis == n_filters
#define NG      64      // n_gauss
#define TS      4096    // filter table samples over [0, CUTOFF]
#define CUTOFFF 5.0f
#define ASTR    132     // smem stride (words) for A tiles (64 rows)
#define BSTR    136     // smem stride (words) for B tiles (128 rows)
#define TILEM   64      // row-tile size
#define PGRID   148     // persistent grid (1 CTA/SM)

// Scratch (no allocations allowed in kernel_launch)
__device__ __half2 g_tabh[(size_t)TS * NB];     // 2 MB  (value, delta) per column
__device__ __half2 g_rfh[(size_t)ATOMS * 64];   // 12.8MB r @ W_af in fp16
__device__ float   g_acc[(size_t)ATOMS * NB];   // 25.6MB segment-sum accumulator

// ---------------------------------------------------------------------------
__device__ __forceinline__ uint32_t smem_u32(const void* p) {
    uint32_t a;
    asm("{ .reg .u64 t; cvta.to.shared.u64 t, %1; cvt.u32.u64 %0, t; }"
        : "=r"(a) : "l"(p));
    return a;
}

// ---------------------------------------------------------------------------
__global__ void zero_acc_kernel() {
    size_t n4 = (size_t)ATOMS * NB / 4;
    float4 z = make_float4(0.f, 0.f, 0.f, 0.f);
    float4* p = reinterpret_cast<float4*>(g_acc);
    for (size_t i = blockIdx.x * (size_t)blockDim.x + threadIdx.x; i < n4;
         i += (size_t)gridDim.x * blockDim.x)
        p[i] = z;
}

// ---------------------------------------------------------------------------
// Build packed fp16 table: tabh[i][c] = (W(d_i)[c], W(d_{i+1})[c]-W(d_i)[c])
__global__ void build_table_kernel(const float* __restrict__ Wdf2,
                                   const float* __restrict__ bdf2) {
    int row  = blockIdx.x * 4 + (threadIdx.x >> 5);
    int lane = threadIdx.x & 31;
    if (row >= TS) return;
    const float step  = CUTOFFF / (float)(TS - 1);
    const float width = 5.0f / 63.0f;
    const float coeff = -0.5f / (width * width);
    float d0 = (float)row * step;
    float d1 = d0 + step;
    float4 a0 = reinterpret_cast<const float4*>(bdf2)[lane];
    float4 a1 = a0;
    #pragma unroll 8
    for (int k = 0; k < NG; k++) {
        float off = (float)k * (5.0f / 63.0f);
        float e0 = d0 - off, e1 = d1 - off;
        float g0 = __expf(coeff * e0 * e0);
        float g1 = __expf(coeff * e1 * e1);
        float4 w = reinterpret_cast<const float4*>(Wdf2 + k * NB)[lane];
        a0.x += g0 * w.x; a0.y += g0 * w.y; a0.z += g0 * w.z; a0.w += g0 * w.w;
        a1.x += g1 * w.x; a1.y += g1 * w.y; a1.z += g1 * w.z; a1.w += g1 * w.w;
    }
    __half2 h[4];
    h[0] = __floats2half2_rn(a0.x, a1.x - a0.x);
    h[1] = __floats2half2_rn(a0.y, a1.y - a0.y);
    h[2] = __floats2half2_rn(a0.z, a1.z - a0.z);
    h[3] = __floats2half2_rn(a0.w, a1.w - a0.w);
    *reinterpret_cast<uint4*>(g_tabh + (size_t)row * NB + lane * 4) =
        *reinterpret_cast<uint4*>(h);
}

// ---------------------------------------------------------------------------
// Edge kernel: warp per edge, 2 edges in flight per iteration.
// Lane owns 4 filter columns: one 16B table load (value,delta pairs) and
// one 8B fp16 rf load; lerp+modulate in fp32; v4 atomic into acc[dst].
__device__ __forceinline__ void edge_compute(int lane, float d, int dst,
                                             int src) {
    const float scale = (float)(TS - 1) / CUTOFFF;
    float pos = d * scale;
    int i = (int)pos;
    i = (i < 0) ? 0 : ((i > TS - 2) ? TS - 2 : i);
    float f = pos - (float)i;
    uint4 t = __ldg(reinterpret_cast<const uint4*>(
        g_tabh + (size_t)i * NB + lane * 4));
    uint2 rr = __ldg(reinterpret_cast<const uint2*>(
        g_rfh + (size_t)src * 64 + lane * 2));
    const __half2* h = reinterpret_cast<const __half2*>(&t);
    const __half2* rh = reinterpret_cast<const __half2*>(&rr);
    float2 p0 = __half22float2(h[0]);
    float2 p1 = __half22float2(h[1]);
    float2 p2 = __half22float2(h[2]);
    float2 p3 = __half22float2(h[3]);
    float2 r0 = __half22float2(rh[0]);
    float2 r1 = __half22float2(rh[1]);
    float4 v;
    v.x = fmaf(f, p0.y, p0.x) * r0.x;
    v.y = fmaf(f, p1.y, p1.x) * r0.y;
    v.z = fmaf(f, p2.y, p2.x) * r1.x;
    v.w = fmaf(f, p3.y, p3.x) * r1.y;
    float* dp = g_acc + (size_t)dst * NB + lane * 4;
    asm volatile("red.global.add.v4.f32 [%0], {%1,%2,%3,%4};"
                 :: "l"(dp), "f"(v.x), "f"(v.y), "f"(v.z), "f"(v.w)
                 : "memory");
}

__global__ void edge_kernel(const float* __restrict__ dist,
                            const int*   __restrict__ idx,
                            int E) {
    int lane   = threadIdx.x & 31;
    int warp   = (blockIdx.x * blockDim.x + threadIdx.x) >> 5;
    int nwarps = (gridDim.x * blockDim.x) >> 5;
    for (int e = warp; e < E; e += 2 * nwarps) {
        int eb = e + nwarps;
        bool hb = eb < E;
        float da = __ldg(&dist[e]);
        int2 ia = *reinterpret_cast<const int2*>(idx + 2 * (size_t)e);
        float db = 0.f;
        int2 ib = make_int2(0, 0);
        if (hb) {
            db = __ldg(&dist[eb]);
            ib = *reinterpret_cast<const int2*>(idx + 2 * (size_t)eb);
        }
        edge_compute(lane, da, ia.x, ia.y);
        if (hb) edge_compute(lane, db, ib.x, ib.y);
    }
}

// ---------------------------------------------------------------------------
__device__ __forceinline__ float sspf(float x) {
    float ax = fabsf(x);
    return fmaxf(x, 0.0f) + log1pf(__expf(-ax)) - 0.69314718f;
}

__device__ __forceinline__ uint32_t f2tf32(float x) {
    uint32_t r;
    asm("cvt.rna.tf32.f32 %0, %1;" : "=r"(r) : "f"(x));
    return r;
}

__device__ __forceinline__ void mma_tf32(float* c, const uint32_t* a,
                                         uint32_t b0, uint32_t b1) {
    asm volatile(
        "mma.sync.aligned.m16n8k8.row.col.f32.tf32.tf32.f32 "
        "{%0,%1,%2,%3}, {%4,%5,%6,%7}, {%8,%9}, {%0,%1,%2,%3};"
        : "+f"(c[0]), "+f"(c[1]), "+f"(c[2]), "+f"(c[3])
        : "r"(a[0]), "r"(a[1]), "r"(a[2]), "r"(a[3]), "r"(b0), "r"(b1));
}

// Stage B[128,128] fp32 -> tf32 smem tile (once per persistent CTA)
__device__ __forceinline__ void stage_B(const float* __restrict__ B,
                                        uint32_t* Bs, int tid) {
    for (int i = tid; i < 128 * 32; i += 256) {
        int r = i >> 5, c = i & 31;
        float4 v = reinterpret_cast<const float4*>(B + r * NB)[c];
        uint4 t = make_uint4(f2tf32(v.x), f2tf32(v.y), f2tf32(v.z), f2tf32(v.w));
        *reinterpret_cast<uint4*>(&Bs[r * BSTR + c * 4]) = t;
    }
}

// Async prefetch of one A tile (raw fp32), zero-fill past M.
__device__ __forceinline__ void prefetch_A(const float* __restrict__ A,
                                           uint32_t as_addr, int row0, int M,
                                           int tid) {
    for (int i = tid; i < TILEM * 32; i += 256) {
        int r = i >> 5, c4 = (i & 31) << 2;
        int row = row0 + r;
        int srow = (row < M) ? row : (M - 1);
        const float* src = A + (size_t)srow * NB + c4;
        uint32_t dst = as_addr + (uint32_t)(r * ASTR + c4) * 4u;
        uint32_t ssz = (row < M) ? 16u : 0u;
        asm volatile("cp.async.ca.shared.global [%0], [%1], 16, %2;"
                     :: "r"(dst), "l"(src), "r"(ssz) : "memory");
    }
}
#define CP_COMMIT() asm volatile("cp.async.commit_group;" ::: "memory")
#define CP_WAIT1()  asm volatile("cp.async.wait_group 1;" ::: "memory")

// One 64x128x128 tile pass. CVT: A words are raw fp32, convert at load.
template <bool CVT>
__device__ __forceinline__ void mma_tile(const uint32_t* As, const uint32_t* Bs,
                                         int wm, int wn, int g, int tig,
                                         float acc[8][4]) {
    #pragma unroll
    for (int nt = 0; nt < 8; nt++)
        #pragma unroll
        for (int j = 0; j < 4; j++) acc[nt][j] = 0.f;

    #pragma unroll
    for (int k0 = 0; k0 < 128; k0 += 8) {
        uint32_t af[4];
        int r = wm * 16;
        af[0] = As[(r + g)     * ASTR + k0 + tig];
        af[1] = As[(r + g + 8) * ASTR + k0 + tig];
        af[2] = As[(r + g)     * ASTR + k0 + tig + 4];
        af[3] = As[(r + g + 8) * ASTR + k0 + tig + 4];
        if (CVT) {
            #pragma unroll
            for (int j = 0; j < 4; j++)
                af[j] = f2tf32(__uint_as_float(af[j]));
        }
        #pragma unroll
        for (int nt = 0; nt < 8; nt++) {
            int n = wn * 64 + nt * 8;
            uint32_t b0 = Bs[(k0 + tig)     * BSTR + n + g];
            uint32_t b1 = Bs[(k0 + tig + 4) * BSTR + n + g];
            mma_tf32(acc[nt], af, b0, b1);
        }
    }
}

// ---------------------------------------------------------------------------
// Persistent GEMM1: rf(fp16) = r @ W_af. B staged once, A double-buffered.
__global__ __launch_bounds__(256, 1)
void gemm_p_kernel(const float* __restrict__ A, const float* __restrict__ B,
                   __half2* __restrict__ C, int M, int ntiles) {
    extern __shared__ uint32_t smu[];
    uint32_t* As0 = smu;                       // [TILEM][ASTR] raw fp32
    uint32_t* As1 = smu + TILEM * ASTR;
    uint32_t* Bs  = smu + 2 * TILEM * ASTR;    // [128][BSTR] tf32
    uint32_t as_addr0 = smem_u32(As0);
    uint32_t as_addr1 = smem_u32(As1);
    int tid = threadIdx.x;

    stage_B(B, Bs, tid);

    int warp = tid >> 5, lane = tid & 31;
    int wm = warp & 3, wn = warp >> 2;
    int g = lane >> 2, tig = lane & 3;

    int t = blockIdx.x;
    int buf = 0;
    if (t < ntiles) prefetch_A(A, as_addr0, t * TILEM, M, tid);
    CP_COMMIT();

    while (t < ntiles) {
        int tn = t + gridDim.x;
        if (tn < ntiles)
            prefetch_A(A, buf ? as_addr0 : as_addr1, tn * TILEM, M, tid);
        CP_COMMIT();
        CP_WAIT1();
        __syncthreads();

        const uint32_t* Asc = buf ? As1 : As0;
        float acc[8][4];
        mma_tile<true>(Asc, Bs, wm, wn, g, tig, acc);

        int row0 = t * TILEM;
        #pragma unroll
        for (int nt = 0; nt < 8; nt++) {
            int col = wn * 64 + nt * 8 + 2 * tig;
            int r1 = row0 + wm * 16 + g, r2 = r1 + 8;
            if (r1 < M)
                C[(size_t)r1 * 64 + (col >> 1)] =
                    __floats2half2_rn(acc[nt][0], acc[nt][1]);
            if (r2 < M)
                C[(size_t)r2 * 64 + (col >> 1)] =
                    __floats2half2_rn(acc[nt][2], acc[nt][3]);
        }
        __syncthreads();   // all reads of Asc done before it is re-prefetched
        buf ^= 1;
        t = tn;
    }
}

// ---------------------------------------------------------------------------
// Persistent fused GEMM2+3: out = ssp(A@W1+b1) @ W2 + b2.
__global__ __launch_bounds__(256, 1)
void gemm23_p_kernel(const float* __restrict__ A,
                     const float* __restrict__ W1, const float* __restrict__ b1,
                     const float* __restrict__ W2, const float* __restrict__ b2,
                     float* __restrict__ C, int M, int ntiles) {
    extern __shared__ uint32_t smu[];
    uint32_t* As0 = smu;
    uint32_t* As1 = smu + TILEM * ASTR;
    uint32_t* B1s = smu + 2 * TILEM * ASTR;
    uint32_t* B2s = B1s + 128 * BSTR;
    uint32_t as_addr0 = smem_u32(As0);
    uint32_t as_addr1 = smem_u32(As1);
    int tid = threadIdx.x;

    stage_B(W1, B1s, tid);
    stage_B(W2, B2s, tid);

    int warp = tid >> 5, lane = tid & 31;
    int wm = warp & 3, wn = warp >> 2;
    int g = lane >> 2, tig = lane & 3;

    int t = blockIdx.x;
    int buf = 0;
    if (t < ntiles) prefetch_A(A, as_addr0, t * TILEM, M, tid);
    CP_COMMIT();

    while (t < ntiles) {
        int tn = t + gridDim.x;
        if (tn < ntiles)
            prefetch_A(A, buf ? as_addr0 : as_addr1, tn * TILEM, M, tid);
        CP_COMMIT();
        CP_WAIT1();
        __syncthreads();

        uint32_t* Asc = buf ? As1 : As0;
        float acc[8][4];

        // Pass 1: mid = ssp(A @ W1 + b1)
        mma_tile<true>(Asc, B1s, wm, wn, g, tig, acc);
        __syncthreads();   // all warps done reading raw A before overwrite

        #pragma unroll
        for (int nt = 0; nt < 8; nt++) {
            int col = wn * 64 + nt * 8 + 2 * tig;
            float2 bv = *reinterpret_cast<const float2*>(b1 + col);
            int r1 = wm * 16 + g, r2 = r1 + 8;
            Asc[r1 * ASTR + col]     = f2tf32(sspf(acc[nt][0] + bv.x));
            Asc[r1 * ASTR + col + 1] = f2tf32(sspf(acc[nt][1] + bv.y));
            Asc[r2 * ASTR + col]     = f2tf32(sspf(acc[nt][2] + bv.x));
            Asc[r2 * ASTR + col + 1] = f2tf32(sspf(acc[nt][3] + bv.y));
        }
        __syncthreads();

        // Pass 2: out = mid @ W2 + b2
        mma_tile<false>(Asc, B2s, wm, wn, g, tig, acc);
        int row0 = t * TILEM;
        #pragma unroll
        for (int nt = 0; nt < 8; nt++) {
            int col = wn * 64 + nt * 8 + 2 * tig;
            float2 bv = *reinterpret_cast<const float2*>(b2 + col);
            int r1 = row0 + wm * 16 + g, r2 = r1 + 8;
            if (r1 < M)
                *reinterpret_cast<float2*>(C + (size_t)r1 * NB + col) =
                    make_float2(acc[nt][0] + bv.x, acc[nt][1] + bv.y);
            if (r2 < M)
                *reinterpret_cast<float2*>(C + (size_t)r2 * NB + col) =
                    make_float2(acc[nt][2] + bv.x, acc[nt][3] + bv.y);
        }
        __syncthreads();
        buf ^= 1;
        t = tn;
    }
}

// ---------------------------------------------------------------------------
extern "C" void kernel_launch(void* const* d_in, const int* in_sizes, int n_in,
                              void* d_out, int out_size) {
    const float* r     = (const float*)d_in[0];
    const float* e     = (const float*)d_in[1];
    const int*   a     = (const int*)  d_in[2];
    // d_in[3], d_in[4] = W_df1, b_df1: dead in the reference (overwritten)
    const float* W_df2 = (const float*)d_in[5];
    const float* b_df2 = (const float*)d_in[6];
    const float* W_af  = (const float*)d_in[7];
    const float* W_d1  = (const float*)d_in[8];
    const float* b_d1  = (const float*)d_in[9];
    const float* W_d2  = (const float*)d_in[10];
    const float* b_d2  = (const float*)d_in[11];
    float* out = (float*)d_out;

    __half2* rfh;
    float*   acc;
    cudaGetSymbolAddress((void**)&rfh, g_rfh);
    cudaGetSymbolAddress((void**)&acc, g_acc);

    const int smem1 = (2 * TILEM * ASTR + 128 * BSTR) * 4;     // 137216 B
    const int smem2 = (2 * TILEM * ASTR + 2 * 128 * BSTR) * 4; // 206848 B
    cudaFuncSetAttribute(gemm_p_kernel,
                         cudaFuncAttributeMaxDynamicSharedMemorySize, smem1);
    cudaFuncSetAttribute(gemm23_p_kernel,
                         cudaFuncAttributeMaxDynamicSharedMemorySize, smem2);

    int E = in_sizes[1];            // 800000
    int M = in_sizes[0] / NB;       // 50000
    int ntiles = (M + TILEM - 1) / TILEM;   // 782

    zero_acc_kernel<<<512, 256>>>();
    build_table_kernel<<<TS / 4, 128>>>(W_df2, b_df2);
    gemm_p_kernel<<<PGRID, 256, smem1>>>(r, W_af, rfh, M, ntiles);
    edge_kernel<<<2048, 256>>>(e, a, E);
    gemm23_p_kernel<<<PGRID, 256, smem2>>>(acc, W_d1, b_d1, W_d2, b_d2,
                                           out, M, ntiles);
}

// round 9
// speedup vs baseline: 1.9128x; 1.0342x over previous
#include <cuda_runtime.h>
#include <cuda_fp16.h>
#include <cstdint>
#include <cstddef>

#define ATOMS   50000
#define EDGES   800000
#define NB      128     // n_atom_basis == n_filters
#define NG      64      // n_gauss
#define TS      4096    // filter table samples over [0, CUTOFF]
#define CUTOFFF 5.0f
#define ASTR    132     // smem stride (words) for A tiles (64 rows, fp32)
#define BS2     68      // smem stride (words) for fp16 B tiles (n-major, k-packed)
#define TILEM   64      // row-tile size
#define PGRID   148     // persistent grid base (1 CTA/SM)

// Scratch (no allocations allowed in kernel_launch)
__device__ __half2 g_tabh[(size_t)TS * NB];     // 2 MB  (value, delta) per column
__device__ __half2 g_rfh[(size_t)ATOMS * 64];   // 12.8MB r @ W_af in fp16
__device__ float   g_acc[(size_t)ATOMS * NB];   // 25.6MB segment-sum accumulator

// ---------------------------------------------------------------------------
__device__ __forceinline__ uint32_t smem_u32(const void* p) {
    uint32_t a;
    asm("{ .reg .u64 t; cvta.to.shared.u64 t, %1; cvt.u32.u64 %0, t; }"
        : "=r"(a) : "l"(p));
    return a;
}

// ---------------------------------------------------------------------------
__global__ void zero_acc_kernel() {
    size_t n4 = (size_t)ATOMS * NB / 4;
    float4 z = make_float4(0.f, 0.f, 0.f, 0.f);
    float4* p = reinterpret_cast<float4*>(g_acc);
    for (size_t i = blockIdx.x * (size_t)blockDim.x + threadIdx.x; i < n4;
         i += (size_t)gridDim.x * blockDim.x)
        p[i] = z;
}

// ---------------------------------------------------------------------------
// Build packed fp16 table: tabh[i][c] = (W(d_i)[c], W(d_{i+1})[c]-W(d_i)[c])
__global__ void build_table_kernel(const float* __restrict__ Wdf2,
                                   const float* __restrict__ bdf2) {
    int row  = blockIdx.x * 4 + (threadIdx.x >> 5);
    int lane = threadIdx.x & 31;
    if (row >= TS) return;
    const float step  = CUTOFFF / (float)(TS - 1);
    const float width = 5.0f / 63.0f;
    const float coeff = -0.5f / (width * width);
    float d0 = (float)row * step;
    float d1 = d0 + step;
    float4 a0 = reinterpret_cast<const float4*>(bdf2)[lane];
    float4 a1 = a0;
    #pragma unroll 8
    for (int k = 0; k < NG; k++) {
        float off = (float)k * (5.0f / 63.0f);
        float e0 = d0 - off, e1 = d1 - off;
        float g0 = __expf(coeff * e0 * e0);
        float g1 = __expf(coeff * e1 * e1);
        float4 w = reinterpret_cast<const float4*>(Wdf2 + k * NB)[lane];
        a0.x += g0 * w.x; a0.y += g0 * w.y; a0.z += g0 * w.z; a0.w += g0 * w.w;
        a1.x += g1 * w.x; a1.y += g1 * w.y; a1.z += g1 * w.z; a1.w += g1 * w.w;
    }
    __half2 h[4];
    h[0] = __floats2half2_rn(a0.x, a1.x - a0.x);
    h[1] = __floats2half2_rn(a0.y, a1.y - a0.y);
    h[2] = __floats2half2_rn(a0.z, a1.z - a0.z);
    h[3] = __floats2half2_rn(a0.w, a1.w - a0.w);
    *reinterpret_cast<uint4*>(g_tabh + (size_t)row * NB + lane * 4) =
        *reinterpret_cast<uint4*>(h);
}

// ---------------------------------------------------------------------------
// Edge kernel (unchanged from R8): warp per edge, 2 edges in flight.
__device__ __forceinline__ void edge_compute(int lane, float d, int dst,
                                             int src) {
    const float scale = (float)(TS - 1) / CUTOFFF;
    float pos = d * scale;
    int i = (int)pos;
    i = (i < 0) ? 0 : ((i > TS - 2) ? TS - 2 : i);
    float f = pos - (float)i;
    uint4 t = __ldg(reinterpret_cast<const uint4*>(
        g_tabh + (size_t)i * NB + lane * 4));
    uint2 rr = __ldg(reinterpret_cast<const uint2*>(
        g_rfh + (size_t)src * 64 + lane * 2));
    const __half2* h = reinterpret_cast<const __half2*>(&t);
    const __half2* rh = reinterpret_cast<const __half2*>(&rr);
    float2 p0 = __half22float2(h[0]);
    float2 p1 = __half22float2(h[1]);
    float2 p2 = __half22float2(h[2]);
    float2 p3 = __half22float2(h[3]);
    float2 r0 = __half22float2(rh[0]);
    float2 r1 = __half22float2(rh[1]);
    float4 v;
    v.x = fmaf(f, p0.y, p0.x) * r0.x;
    v.y = fmaf(f, p1.y, p1.x) * r0.y;
    v.z = fmaf(f, p2.y, p2.x) * r1.x;
    v.w = fmaf(f, p3.y, p3.x) * r1.y;
    float* dp = g_acc + (size_t)dst * NB + lane * 4;
    asm volatile("red.global.add.v4.f32 [%0], {%1,%2,%3,%4};"
                 :: "l"(dp), "f"(v.x), "f"(v.y), "f"(v.z), "f"(v.w)
                 : "memory");
}

__global__ void edge_kernel(const float* __restrict__ dist,
                            const int*   __restrict__ idx,
                            int E) {
    int lane   = threadIdx.x & 31;
    int warp   = (blockIdx.x * blockDim.x + threadIdx.x) >> 5;
    int nwarps = (gridDim.x * blockDim.x) >> 5;
    for (int e = warp; e < E; e += 2 * nwarps) {
        int eb = e + nwarps;
        bool hb = eb < E;
        float da = __ldg(&dist[e]);
        int2 ia = *reinterpret_cast<const int2*>(idx + 2 * (size_t)e);
        float db = 0.f;
        int2 ib = make_int2(0, 0);
        if (hb) {
            db = __ldg(&dist[eb]);
            ib = *reinterpret_cast<const int2*>(idx + 2 * (size_t)eb);
        }
        edge_compute(lane, da, ia.x, ia.y);
        if (hb) edge_compute(lane, db, ib.x, ib.y);
    }
}

// ---------------------------------------------------------------------------
__device__ __forceinline__ float sspf(float x) {
    float ax = fabsf(x);
    return fmaxf(x, 0.0f) + log1pf(__expf(-ax)) - 0.69314718f;
}

// fp16 m16n8k16 MMA, fp32 accumulate
__device__ __forceinline__ void mma_f16(float* c, const uint32_t* a,
                                        uint32_t b0, uint32_t b1) {
    asm volatile(
        "mma.sync.aligned.m16n8k16.row.col.f32.f16.f16.f32 "
        "{%0,%1,%2,%3}, {%4,%5,%6,%7}, {%8,%9}, {%0,%1,%2,%3};"
        : "+f"(c[0]), "+f"(c[1]), "+f"(c[2]), "+f"(c[3])
        : "r"(a[0]), "r"(a[1]), "r"(a[2]), "r"(a[3]), "r"(b0), "r"(b1));
}

__device__ __forceinline__ uint32_t packh2(float x, float y) {
    __half2 h = __floats2half2_rn(x, y);
    return *reinterpret_cast<uint32_t*>(&h);
}

// Stage W[128,128] fp32 (k-major) -> fp16 n-major packed smem: Bh[n][k],
// stride 2*BS2 halves per n-row. One-time per persistent CTA.
__device__ __forceinline__ void stage_B_h(const float* __restrict__ W,
                                          __half* Bh, int tid) {
    for (int i = tid; i < 128 * 32; i += 256) {
        int k = i >> 5, c = i & 31;
        int n0 = c * 4;
        float4 v = reinterpret_cast<const float4*>(W + k * NB)[c];
        Bh[(n0 + 0) * (2 * BS2) + k] = __float2half_rn(v.x);
        Bh[(n0 + 1) * (2 * BS2) + k] = __float2half_rn(v.y);
        Bh[(n0 + 2) * (2 * BS2) + k] = __float2half_rn(v.z);
        Bh[(n0 + 3) * (2 * BS2) + k] = __float2half_rn(v.w);
    }
}

// Async prefetch of one A tile (raw fp32), zero-fill past M.
__device__ __forceinline__ void prefetch_A(const float* __restrict__ A,
                                           uint32_t as_addr, int row0, int M,
                                           int tid) {
    for (int i = tid; i < TILEM * 32; i += 256) {
        int r = i >> 5, c4 = (i & 31) << 2;
        int row = row0 + r;
        int srow = (row < M) ? row : (M - 1);
        const float* src = A + (size_t)srow * NB + c4;
        uint32_t dst = as_addr + (uint32_t)(r * ASTR + c4) * 4u;
        uint32_t ssz = (row < M) ? 16u : 0u;
        asm volatile("cp.async.ca.shared.global [%0], [%1], 16, %2;"
                     :: "r"(dst), "l"(src), "r"(ssz) : "memory");
    }
}
#define CP_COMMIT() asm volatile("cp.async.commit_group;" ::: "memory")
#define CP_WAIT1()  asm volatile("cp.async.wait_group 1;" ::: "memory")

// One 64x128x128 tile pass with fp16 m16n8k16. A: fp32 smem (cvt at load);
// B: fp16 packed n-major. Warp tile 16x64; acc[nt][4] for 8 n-tiles.
__device__ __forceinline__ void mma_tile_h(const uint32_t* As,
                                           const uint32_t* Bs,
                                           int wm, int wn, int g, int tig,
                                           float acc[8][4]) {
    #pragma unroll
    for (int nt = 0; nt < 8; nt++)
        #pragma unroll
        for (int j = 0; j < 4; j++) acc[nt][j] = 0.f;

    #pragma unroll
    for (int k0 = 0; k0 < 128; k0 += 16) {
        uint32_t af[4];
        int r = wm * 16;
        float2 x;
        x = *reinterpret_cast<const float2*>(&As[(r + g)     * ASTR + k0 + 2 * tig]);
        af[0] = packh2(x.x, x.y);
        x = *reinterpret_cast<const float2*>(&As[(r + g + 8) * ASTR + k0 + 2 * tig]);
        af[1] = packh2(x.x, x.y);
        x = *reinterpret_cast<const float2*>(&As[(r + g)     * ASTR + k0 + 2 * tig + 8]);
        af[2] = packh2(x.x, x.y);
        x = *reinterpret_cast<const float2*>(&As[(r + g + 8) * ASTR + k0 + 2 * tig + 8]);
        af[3] = packh2(x.x, x.y);
        #pragma unroll
        for (int nt = 0; nt < 8; nt++) {
            int n = wn * 64 + nt * 8 + g;
            uint32_t b0 = Bs[n * BS2 + (k0 >> 1) + tig];
            uint32_t b1 = Bs[n * BS2 + (k0 >> 1) + tig + 4];
            mma_f16(acc[nt], af, b0, b1);
        }
    }
}

// ---------------------------------------------------------------------------
// Persistent GEMM1: rf(fp16) = r @ W_af. 2 CTAs/SM.
__global__ __launch_bounds__(256, 2)
void gemm_p_kernel(const float* __restrict__ A, const float* __restrict__ B,
                   __half2* __restrict__ C, int M, int ntiles) {
    extern __shared__ uint32_t smu[];
    uint32_t* As0 = smu;                       // [TILEM][ASTR] raw fp32
    uint32_t* As1 = smu + TILEM * ASTR;
    uint32_t* Bs  = smu + 2 * TILEM * ASTR;    // [128][BS2] fp16x2
    uint32_t as_addr0 = smem_u32(As0);
    uint32_t as_addr1 = smem_u32(As1);
    int tid = threadIdx.x;

    stage_B_h(B, reinterpret_cast<__half*>(Bs), tid);

    int warp = tid >> 5, lane = tid & 31;
    int wm = warp & 3, wn = warp >> 2;
    int g = lane >> 2, tig = lane & 3;

    int t = blockIdx.x;
    int buf = 0;
    if (t < ntiles) prefetch_A(A, as_addr0, t * TILEM, M, tid);
    CP_COMMIT();

    while (t < ntiles) {
        int tn = t + gridDim.x;
        if (tn < ntiles)
            prefetch_A(A, buf ? as_addr0 : as_addr1, tn * TILEM, M, tid);
        CP_COMMIT();
        CP_WAIT1();
        __syncthreads();

        const uint32_t* Asc = buf ? As1 : As0;
        float acc[8][4];
        mma_tile_h(Asc, Bs, wm, wn, g, tig, acc);

        int row0 = t * TILEM;
        #pragma unroll
        for (int nt = 0; nt < 8; nt++) {
            int col = wn * 64 + nt * 8 + 2 * tig;
            int r1 = row0 + wm * 16 + g, r2 = r1 + 8;
            if (r1 < M)
                C[(size_t)r1 * 64 + (col >> 1)] =
                    __floats2half2_rn(acc[nt][0], acc[nt][1]);
            if (r2 < M)
                C[(size_t)r2 * 64 + (col >> 1)] =
                    __floats2half2_rn(acc[nt][2], acc[nt][3]);
        }
        __syncthreads();   // reads of Asc done before it is re-prefetched
        buf ^= 1;
        t = tn;
    }
}

// ---------------------------------------------------------------------------
// Persistent fused GEMM2+3: out = ssp(A@W1+b1) @ W2 + b2. Mid stored fp32
// in the consumed A buffer between passes.
__global__ __launch_bounds__(256, 1)
void gemm23_p_kernel(const float* __restrict__ A,
                     const float* __restrict__ W1, const float* __restrict__ b1,
                     const float* __restrict__ W2, const float* __restrict__ b2,
                     float* __restrict__ C, int M, int ntiles) {
    extern __shared__ uint32_t smu[];
    uint32_t* As0 = smu;
    uint32_t* As1 = smu + TILEM * ASTR;
    uint32_t* B1s = smu + 2 * TILEM * ASTR;
    uint32_t* B2s = B1s + 128 * BS2;
    uint32_t as_addr0 = smem_u32(As0);
    uint32_t as_addr1 = smem_u32(As1);
    int tid = threadIdx.x;

    stage_B_h(W1, reinterpret_cast<__half*>(B1s), tid);
    stage_B_h(W2, reinterpret_cast<__half*>(B2s), tid);

    int warp = tid >> 5, lane = tid & 31;
    int wm = warp & 3, wn = warp >> 2;
    int g = lane >> 2, tig = lane & 3;

    int t = blockIdx.x;
    int buf = 0;
    if (t < ntiles) prefetch_A(A, as_addr0, t * TILEM, M, tid);
    CP_COMMIT();

    while (t < ntiles) {
        int tn = t + gridDim.x;
        if (tn < ntiles)
            prefetch_A(A, buf ? as_addr0 : as_addr1, tn * TILEM, M, tid);
        CP_COMMIT();
        CP_WAIT1();
        __syncthreads();

        uint32_t* Asc = buf ? As1 : As0;
        float acc[8][4];

        // Pass 1: mid = ssp(A @ W1 + b1)
        mma_tile_h(Asc, B1s, wm, wn, g, tig, acc);
        __syncthreads();   // all warps done reading raw A before overwrite

        #pragma unroll
        for (int nt = 0; nt < 8; nt++) {
            int col = wn * 64 + nt * 8 + 2 * tig;
            float2 bv = *reinterpret_cast<const float2*>(b1 + col);
            int r1 = wm * 16 + g, r2 = r1 + 8;
            Asc[r1 * ASTR + col]     = __float_as_uint(sspf(acc[nt][0] + bv.x));
            Asc[r1 * ASTR + col + 1] = __float_as_uint(sspf(acc[nt][1] + bv.y));
            Asc[r2 * ASTR + col]     = __float_as_uint(sspf(acc[nt][2] + bv.x));
            Asc[r2 * ASTR + col + 1] = __float_as_uint(sspf(acc[nt][3] + bv.y));
        }
        __syncthreads();

        // Pass 2: out = mid @ W2 + b2
        mma_tile_h(Asc, B2s, wm, wn, g, tig, acc);
        int row0 = t * TILEM;
        #pragma unroll
        for (int nt = 0; nt < 8; nt++) {
            int col = wn * 64 + nt * 8 + 2 * tig;
            float2 bv = *reinterpret_cast<const float2*>(b2 + col);
            int r1 = row0 + wm * 16 + g, r2 = r1 + 8;
            if (r1 < M)
                *reinterpret_cast<float2*>(C + (size_t)r1 * NB + col) =
                    make_float2(acc[nt][0] + bv.x, acc[nt][1] + bv.y);
            if (r2 < M)
                *reinterpret_cast<float2*>(C + (size_t)r2 * NB + col) =
                    make_float2(acc[nt][2] + bv.x, acc[nt][3] + bv.y);
        }
        __syncthreads();
        buf ^= 1;
        t = tn;
    }
}

// ---------------------------------------------------------------------------
extern "C" void kernel_launch(void* const* d_in, const int* in_sizes, int n_in,
                              void* d_out, int out_size) {
    const float* r     = (const float*)d_in[0];
    const float* e     = (const float*)d_in[1];
    const int*   a     = (const int*)  d_in[2];
    // d_in[3], d_in[4] = W_df1, b_df1: dead in the reference (overwritten)
    const float* W_df2 = (const float*)d_in[5];
    const float* b_df2 = (const float*)d_in[6];
    const float* W_af  = (const float*)d_in[7];
    const float* W_d1  = (const float*)d_in[8];
    const float* b_d1  = (const float*)d_in[9];
    const float* W_d2  = (const float*)d_in[10];
    const float* b_d2  = (const float*)d_in[11];
    float* out = (float*)d_out;

    __half2* rfh;
    float*   acc;
    cudaGetSymbolAddress((void**)&rfh, g_rfh);
    cudaGetSymbolAddress((void**)&acc, g_acc);

    const int smem1 = (2 * TILEM * ASTR + 128 * BS2) * 4;      // 102400 B
    const int smem2 = (2 * TILEM * ASTR + 2 * 128 * BS2) * 4;  // 137216 B
    cudaFuncSetAttribute(gemm_p_kernel,
                         cudaFuncAttributeMaxDynamicSharedMemorySize, smem1);
    cudaFuncSetAttribute(gemm23_p_kernel,
                         cudaFuncAttributeMaxDynamicSharedMemorySize, smem2);

    int E = in_sizes[1];            // 800000
    int M = in_sizes[0] / NB;       // 50000
    int ntiles = (M + TILEM - 1) / TILEM;   // 782

    zero_acc_kernel<<<512, 256>>>();
    build_table_kernel<<<TS / 4, 128>>>(W_df2, b_df2);
    gemm_p_kernel<<<2 * PGRID, 256, smem1>>>(r, W_af, rfh, M, ntiles);
    edge_kernel<<<2048, 256>>>(e, a, E);
    gemm23_p_kernel<<<PGRID, 256, smem2>>>(acc, W_d1, b_d1, W_d2, b_d2,
                                           out, M, ntiles);
}

// round 10
// speedup vs baseline: 2.0484x; 1.0709x over previous
#include <cuda_runtime.h>
#include <cuda_fp16.h>
#include <cstdint>
#include <cstddef>

#define ATOMS   50000
#define EDGES   800000
#define NB      128     // n_atom_basis == n_filters
#define NG      64      // n_gauss
#define TS      4096    // filter table samples over [0, CUTOFF]
#define CUTOFFF 5.0f
#define ASTR    132     // smem stride (words) for A tiles (64 rows, fp32)
#define BS2     68      // smem stride (words) for fp16 B tiles (n-major)
#define TILEM   64      // row-tile size
#define PGRID   148     // persistent grid base (1 CTA/SM)
#define NSCB    196     // scan blocks: 196*256 >= ATOMS

// Scratch (no allocations allowed in kernel_launch)
__device__ __half2 g_tabh[(size_t)TS * NB];     // 2 MB  (value, delta) per column
__device__ __half2 g_rfh[(size_t)ATOMS * 64];   // 12.8MB r @ W_af in fp16
__device__ float   g_acc[(size_t)ATOMS * NB];   // 25.6MB segment-sum result
__device__ int     g_cnt[ATOMS];                // counts, then scatter cursor
__device__ int     g_off[ATOMS + 1];            // CSR offsets
__device__ int     g_bsum[256];                 // scan block sums
__device__ uint2   g_rec[EDGES];                // packed (src, dist-bits)

// ---------------------------------------------------------------------------
__device__ __forceinline__ uint32_t smem_u32(const void* p) {
    uint32_t a;
    asm("{ .reg .u64 t; cvta.to.shared.u64 t, %1; cvt.u32.u64 %0, t; }"
        : "=r"(a) : "l"(p));
    return a;
}

// ---------------------------------------------------------------------------
// Build packed fp16 table; also zeroes g_cnt (1024 blocks x 128 thr covers it).
__global__ void build_table_kernel(const float* __restrict__ Wdf2,
                                   const float* __restrict__ bdf2) {
    int lin = blockIdx.x * 128 + threadIdx.x;
    if (lin < ATOMS) g_cnt[lin] = 0;

    int row  = blockIdx.x * 4 + (threadIdx.x >> 5);
    int lane = threadIdx.x & 31;
    if (row >= TS) return;
    const float step  = CUTOFFF / (float)(TS - 1);
    const float width = 5.0f / 63.0f;
    const float coeff = -0.5f / (width * width);
    float d0 = (float)row * step;
    float d1 = d0 + step;
    float4 a0 = reinterpret_cast<const float4*>(bdf2)[lane];
    float4 a1 = a0;
    #pragma unroll 8
    for (int k = 0; k < NG; k++) {
        float off = (float)k * (5.0f / 63.0f);
        float e0 = d0 - off, e1 = d1 - off;
        float g0 = __expf(coeff * e0 * e0);
        float g1 = __expf(coeff * e1 * e1);
        float4 w = reinterpret_cast<const float4*>(Wdf2 + k * NB)[lane];
        a0.x += g0 * w.x; a0.y += g0 * w.y; a0.z += g0 * w.z; a0.w += g0 * w.w;
        a1.x += g1 * w.x; a1.y += g1 * w.y; a1.z += g1 * w.z; a1.w += g1 * w.w;
    }
    __half2 h[4];
    h[0] = __floats2half2_rn(a0.x, a1.x - a0.x);
    h[1] = __floats2half2_rn(a0.y, a1.y - a0.y);
    h[2] = __floats2half2_rn(a0.z, a1.z - a0.z);
    h[3] = __floats2half2_rn(a0.w, a1.w - a0.w);
    *reinterpret_cast<uint4*>(g_tabh + (size_t)row * NB + lane * 4) =
        *reinterpret_cast<uint4*>(h);
}

// ---------------------------------------------------------------------------
// CSR binning: histogram -> 2-level exclusive scan -> scatter records.
__global__ void hist_kernel(const int* __restrict__ idx, int E) {
    for (int i = blockIdx.x * blockDim.x + threadIdx.x; i < E;
         i += gridDim.x * blockDim.x) {
        int dst = __ldg(&idx[2 * i]);
        atomicAdd(&g_cnt[dst], 1);
    }
}

__global__ void scan1_kernel() {   // per-256-chunk exclusive scan
    __shared__ int sm[256];
    int t = threadIdx.x, i = blockIdx.x * 256 + t;
    int v = (i < ATOMS) ? g_cnt[i] : 0;
    sm[t] = v; __syncthreads();
    #pragma unroll
    for (int d = 1; d < 256; d <<= 1) {
        int x = (t >= d) ? sm[t - d] : 0;
        __syncthreads();
        sm[t] += x;
        __syncthreads();
    }
    if (i < ATOMS) g_off[i] = sm[t] - v;
    if (t == 255) g_bsum[blockIdx.x] = sm[255];
}

__global__ void scan2_kernel() {   // scan the block sums (single block)
    __shared__ int sm[256];
    int t = threadIdx.x;
    int v = (t < NSCB) ? g_bsum[t] : 0;
    sm[t] = v; __syncthreads();
    #pragma unroll
    for (int d = 1; d < 256; d <<= 1) {
        int x = (t >= d) ? sm[t - d] : 0;
        __syncthreads();
        sm[t] += x;
        __syncthreads();
    }
    if (t < NSCB) g_bsum[t] = sm[t] - v;
}

__global__ void scan3_kernel(int E) {  // add block offsets; init cursor
    int i = blockIdx.x * blockDim.x + threadIdx.x;
    if (i < ATOMS) {
        int o = g_off[i] + g_bsum[i >> 8];
        g_off[i] = o;
        g_cnt[i] = o;
    }
    if (i == 0) g_off[ATOMS] = E;
}

__global__ void scatter_kernel(const float* __restrict__ dist,
                               const int* __restrict__ idx, int E) {
    for (int i = blockIdx.x * blockDim.x + threadIdx.x; i < E;
         i += gridDim.x * blockDim.x) {
        int2 de = *reinterpret_cast<const int2*>(idx + 2 * (size_t)i);
        float d = __ldg(&dist[i]);
        int pos = atomicAdd(&g_cnt[de.x], 1);
        g_rec[pos] = make_uint2((uint32_t)de.y, __float_as_uint(d));
    }
}

// ---------------------------------------------------------------------------
// Gather: warp per atom; walk its edge list, accumulate in registers,
// one plain store. No atomics, no acc zeroing needed.
__device__ __forceinline__ void edge_acc(int lane, uint2 rec, float4& acc) {
    const float scale = (float)(TS - 1) / CUTOFFF;
    float d = __uint_as_float(rec.y);
    float pos = d * scale;
    int i = (int)pos;
    i = (i < 0) ? 0 : ((i > TS - 2) ? TS - 2 : i);
    float f = pos - (float)i;
    uint4 t = __ldg(reinterpret_cast<const uint4*>(
        g_tabh + (size_t)i * NB + lane * 4));
    uint2 rr = __ldg(reinterpret_cast<const uint2*>(
        g_rfh + (size_t)rec.x * 64 + lane * 2));
    const __half2* h = reinterpret_cast<const __half2*>(&t);
    const __half2* rh = reinterpret_cast<const __half2*>(&rr);
    float2 p0 = __half22float2(h[0]);
    float2 p1 = __half22float2(h[1]);
    float2 p2 = __half22float2(h[2]);
    float2 p3 = __half22float2(h[3]);
    float2 r0 = __half22float2(rh[0]);
    float2 r1 = __half22float2(rh[1]);
    acc.x = fmaf(fmaf(f, p0.y, p0.x), r0.x, acc.x);
    acc.y = fmaf(fmaf(f, p1.y, p1.x), r0.y, acc.y);
    acc.z = fmaf(fmaf(f, p2.y, p2.x), r1.x, acc.z);
    acc.w = fmaf(fmaf(f, p3.y, p3.x), r1.y, acc.w);
}

__global__ void gather_kernel() {
    int lane   = threadIdx.x & 31;
    int warp   = (blockIdx.x * blockDim.x + threadIdx.x) >> 5;
    int nwarps = (gridDim.x * blockDim.x) >> 5;
    for (int a = warp; a < ATOMS; a += nwarps) {
        int p  = __ldg(&g_off[a]);
        int pe = __ldg(&g_off[a + 1]);
        float4 acc = make_float4(0.f, 0.f, 0.f, 0.f);
        for (; p + 2 <= pe; p += 2) {
            uint2 ra = __ldg(&g_rec[p]);
            uint2 rb = __ldg(&g_rec[p + 1]);
            edge_acc(lane, ra, acc);
            edge_acc(lane, rb, acc);
        }
        if (p < pe) {
            uint2 ra = __ldg(&g_rec[p]);
            edge_acc(lane, ra, acc);
        }
        *reinterpret_cast<float4*>(g_acc + (size_t)a * NB + lane * 4) = acc;
    }
}

// ---------------------------------------------------------------------------
__device__ __forceinline__ float sspf(float x) {
    float ax = fabsf(x);
    return fmaxf(x, 0.0f) + log1pf(__expf(-ax)) - 0.69314718f;
}

__device__ __forceinline__ void mma_f16(float* c, const uint32_t* a,
                                        uint32_t b0, uint32_t b1) {
    asm volatile(
        "mma.sync.aligned.m16n8k16.row.col.f32.f16.f16.f32 "
        "{%0,%1,%2,%3}, {%4,%5,%6,%7}, {%8,%9}, {%0,%1,%2,%3};"
        : "+f"(c[0]), "+f"(c[1]), "+f"(c[2]), "+f"(c[3])
        : "r"(a[0]), "r"(a[1]), "r"(a[2]), "r"(a[3]), "r"(b0), "r"(b1));
}

__device__ __forceinline__ uint32_t packh2(float x, float y) {
    __half2 h = __floats2half2_rn(x, y);
    return *reinterpret_cast<uint32_t*>(&h);
}

__device__ __forceinline__ void stage_B_h(const float* __restrict__ W,
                                          __half* Bh, int tid) {
    for (int i = tid; i < 128 * 32; i += 256) {
        int k = i >> 5, c = i & 31;
        int n0 = c * 4;
        float4 v = reinterpret_cast<const float4*>(W + k * NB)[c];
        Bh[(n0 + 0) * (2 * BS2) + k] = __float2half_rn(v.x);
        Bh[(n0 + 1) * (2 * BS2) + k] = __float2half_rn(v.y);
        Bh[(n0 + 2) * (2 * BS2) + k] = __float2half_rn(v.z);
        Bh[(n0 + 3) * (2 * BS2) + k] = __float2half_rn(v.w);
    }
}

__device__ __forceinline__ void prefetch_A(const float* __restrict__ A,
                                           uint32_t as_addr, int row0, int M,
                                           int tid) {
    for (int i = tid; i < TILEM * 32; i += 256) {
        int r = i >> 5, c4 = (i & 31) << 2;
        int row = row0 + r;
        int srow = (row < M) ? row : (M - 1);
        const float* src = A + (size_t)srow * NB + c4;
        uint32_t dst = as_addr + (uint32_t)(r * ASTR + c4) * 4u;
        uint32_t ssz = (row < M) ? 16u : 0u;
        asm volatile("cp.async.ca.shared.global [%0], [%1], 16, %2;"
                     :: "r"(dst), "l"(src), "r"(ssz) : "memory");
    }
}
#define CP_COMMIT() asm volatile("cp.async.commit_group;" ::: "memory")
#define CP_WAIT1()  asm volatile("cp.async.wait_group 1;" ::: "memory")

__device__ __forceinline__ void mma_tile_h(const uint32_t* As,
                                           const uint32_t* Bs,
                                           int wm, int wn, int g, int tig,
                                           float acc[8][4]) {
    #pragma unroll
    for (int nt = 0; nt < 8; nt++)
        #pragma unroll
        for (int j = 0; j < 4; j++) acc[nt][j] = 0.f;

    #pragma unroll
    for (int k0 = 0; k0 < 128; k0 += 16) {
        uint32_t af[4];
        int r = wm * 16;
        float2 x;
        x = *reinterpret_cast<const float2*>(&As[(r + g)     * ASTR + k0 + 2 * tig]);
        af[0] = packh2(x.x, x.y);
        x = *reinterpret_cast<const float2*>(&As[(r + g + 8) * ASTR + k0 + 2 * tig]);
        af[1] = packh2(x.x, x.y);
        x = *reinterpret_cast<const float2*>(&As[(r + g)     * ASTR + k0 + 2 * tig + 8]);
        af[2] = packh2(x.x, x.y);
        x = *reinterpret_cast<const float2*>(&As[(r + g + 8) * ASTR + k0 + 2 * tig + 8]);
        af[3] = packh2(x.x, x.y);
        #pragma unroll
        for (int nt = 0; nt < 8; nt++) {
            int n = wn * 64 + nt * 8 + g;
            uint32_t b0 = Bs[n * BS2 + (k0 >> 1) + tig];
            uint32_t b1 = Bs[n * BS2 + (k0 >> 1) + tig + 4];
            mma_f16(acc[nt], af, b0, b1);
        }
    }
}

// ---------------------------------------------------------------------------
// Persistent GEMM1: rf(fp16) = r @ W_af. 2 CTAs/SM.
__global__ __launch_bounds__(256, 2)
void gemm_p_kernel(const float* __restrict__ A, const float* __restrict__ B,
                   __half2* __restrict__ C, int M, int ntiles) {
    extern __shared__ uint32_t smu[];
    uint32_t* As0 = smu;
    uint32_t* As1 = smu + TILEM * ASTR;
    uint32_t* Bs  = smu + 2 * TILEM * ASTR;
    uint32_t as_addr0 = smem_u32(As0);
    uint32_t as_addr1 = smem_u32(As1);
    int tid = threadIdx.x;

    stage_B_h(B, reinterpret_cast<__half*>(Bs), tid);

    int warp = tid >> 5, lane = tid & 31;
    int wm = warp & 3, wn = warp >> 2;
    int g = lane >> 2, tig = lane & 3;

    int t = blockIdx.x;
    int buf = 0;
    if (t < ntiles) prefetch_A(A, as_addr0, t * TILEM, M, tid);
    CP_COMMIT();

    while (t < ntiles) {
        int tn = t + gridDim.x;
        if (tn < ntiles)
            prefetch_A(A, buf ? as_addr0 : as_addr1, tn * TILEM, M, tid);
        CP_COMMIT();
        CP_WAIT1();
        __syncthreads();

        const uint32_t* Asc = buf ? As1 : As0;
        float acc[8][4];
        mma_tile_h(Asc, Bs, wm, wn, g, tig, acc);

        int row0 = t * TILEM;
        #pragma unroll
        for (int nt = 0; nt < 8; nt++) {
            int col = wn * 64 + nt * 8 + 2 * tig;
            int r1 = row0 + wm * 16 + g, r2 = r1 + 8;
            if (r1 < M)
                C[(size_t)r1 * 64 + (col >> 1)] =
                    __floats2half2_rn(acc[nt][0], acc[nt][1]);
            if (r2 < M)
                C[(size_t)r2 * 64 + (col >> 1)] =
                    __floats2half2_rn(acc[nt][2], acc[nt][3]);
        }
        __syncthreads();
        buf ^= 1;
        t = tn;
    }
}

// ---------------------------------------------------------------------------
// Persistent fused GEMM2+3: out = ssp(A@W1+b1) @ W2 + b2.
__global__ __launch_bounds__(256, 1)
void gemm23_p_kernel(const float* __restrict__ A,
                     const float* __restrict__ W1, const float* __restrict__ b1,
                     const float* __restrict__ W2, const float* __restrict__ b2,
                     float* __restrict__ C, int M, int ntiles) {
    extern __shared__ uint32_t smu[];
    uint32_t* As0 = smu;
    uint32_t* As1 = smu + TILEM * ASTR;
    uint32_t* B1s = smu + 2 * TILEM * ASTR;
    uint32_t* B2s = B1s + 128 * BS2;
    uint32_t as_addr0 = smem_u32(As0);
    uint32_t as_addr1 = smem_u32(As1);
    int tid = threadIdx.x;

    stage_B_h(W1, reinterpret_cast<__half*>(B1s), tid);
    stage_B_h(W2, reinterpret_cast<__half*>(B2s), tid);

    int warp = tid >> 5, lane = tid & 31;
    int wm = warp & 3, wn = warp >> 2;
    int g = lane >> 2, tig = lane & 3;

    int t = blockIdx.x;
    int buf = 0;
    if (t < ntiles) prefetch_A(A, as_addr0, t * TILEM, M, tid);
    CP_COMMIT();

    while (t < ntiles) {
        int tn = t + gridDim.x;
        if (tn < ntiles)
            prefetch_A(A, buf ? as_addr0 : as_addr1, tn * TILEM, M, tid);
        CP_COMMIT();
        CP_WAIT1();
        __syncthreads();

        uint32_t* Asc = buf ? As1 : As0;
        float acc[8][4];

        // Pass 1: mid = ssp(A @ W1 + b1)
        mma_tile_h(Asc, B1s, wm, wn, g, tig, acc);
        __syncthreads();

        #pragma unroll
        for (int nt = 0; nt < 8; nt++) {
            int col = wn * 64 + nt * 8 + 2 * tig;
            float2 bv = *reinterpret_cast<const float2*>(b1 + col);
            int r1 = wm * 16 + g, r2 = r1 + 8;
            Asc[r1 * ASTR + col]     = __float_as_uint(sspf(acc[nt][0] + bv.x));
            Asc[r1 * ASTR + col + 1] = __float_as_uint(sspf(acc[nt][1] + bv.y));
            Asc[r2 * ASTR + col]     = __float_as_uint(sspf(acc[nt][2] + bv.x));
            Asc[r2 * ASTR + col + 1] = __float_as_uint(sspf(acc[nt][3] + bv.y));
        }
        __syncthreads();

        // Pass 2: out = mid @ W2 + b2
        mma_tile_h(Asc, B2s, wm, wn, g, tig, acc);
        int row0 = t * TILEM;
        #pragma unroll
        for (int nt = 0; nt < 8; nt++) {
            int col = wn * 64 + nt * 8 + 2 * tig;
            float2 bv = *reinterpret_cast<const float2*>(b2 + col);
            int r1 = row0 + wm * 16 + g, r2 = r1 + 8;
            if (r1 < M)
                *reinterpret_cast<float2*>(C + (size_t)r1 * NB + col) =
                    make_float2(acc[nt][0] + bv.x, acc[nt][1] + bv.y);
            if (r2 < M)
                *reinterpret_cast<float2*>(C + (size_t)r2 * NB + col) =
                    make_float2(acc[nt][2] + bv.x, acc[nt][3] + bv.y);
        }
        __syncthreads();
        buf ^= 1;
        t = tn;
    }
}

// ---------------------------------------------------------------------------
extern "C" void kernel_launch(void* const* d_in, const int* in_sizes, int n_in,
                              void* d_out, int out_size) {
    const float* r     = (const float*)d_in[0];
    const float* e     = (const float*)d_in[1];
    const int*   a     = (const int*)  d_in[2];
    // d_in[3], d_in[4] = W_df1, b_df1: dead in the reference (overwritten)
    const float* W_df2 = (const float*)d_in[5];
    const float* b_df2 = (const float*)d_in[6];
    const float* W_af  = (const float*)d_in[7];
    const float* W_d1  = (const float*)d_in[8];
    const float* b_d1  = (const float*)d_in[9];
    const float* W_d2  = (const float*)d_in[10];
    const float* b_d2  = (const float*)d_in[11];
    float* out = (float*)d_out;

    __half2* rfh;
    float*   acc;
    cudaGetSymbolAddress((void**)&rfh, g_rfh);
    cudaGetSymbolAddress((void**)&acc, g_acc);

    const int smem1 = (2 * TILEM * ASTR + 128 * BS2) * 4;      // 102400 B
    const int smem2 = (2 * TILEM * ASTR + 2 * 128 * BS2) * 4;  // 137216 B
    cudaFuncSetAttribute(gemm_p_kernel,
                         cudaFuncAttributeMaxDynamicSharedMemorySize, smem1);
    cudaFuncSetAttribute(gemm23_p_kernel,
                         cudaFuncAttributeMaxDynamicSharedMemorySize, smem2);

    int E = in_sizes[1];            // 800000
    int M = in_sizes[0] / NB;       // 50000
    int ntiles = (M + TILEM - 1) / TILEM;   // 782

    build_table_kernel<<<TS / 4, 128>>>(W_df2, b_df2);   // + zero g_cnt
    gemm_p_kernel<<<2 * PGRID, 256, smem1>>>(r, W_af, rfh, M, ntiles);
    hist_kernel<<<1024, 256>>>(a, E);
    scan1_kernel<<<NSCB, 256>>>();
    scan2_kernel<<<1, 256>>>();
    scan3_kernel<<<NSCB, 256>>>(E);
    scatter_kernel<<<1024, 256>>>(e, a, E);
    gather_kernel<<<1024, 256>>>();
    gemm23_p_kernel<<<PGRID, 256, smem2>>>(acc, W_d1, b_d1, W_d2, b_d2,
                                           out, M, ntiles);
}